// round 12
// baseline (speedup 1.0000x reference)
#include <cuda_runtime.h>
#include <cuda_fp16.h>
#include <math.h>
#include <stdint.h>

// Problem constants
#define Bn   4
#define Sn   1024
#define Dn   1024
#define Hn   16
#define DHn  64
#define DFFn 4096
#define TOK  (Bn*Sn)          // 4096
#define EPSF 1e-5f
#define NEGF (-1e20f)

// ---------------- static device workspaces ----------------
__device__ float g_q [TOK*Dn];     // (kept: gate g fp32 target reuse)
__device__ float g_t1[TOK*Dn];
__device__ float g_t2[TOK*Dn];
__device__ float g_t3[TOK*Dn];
__device__ float g_cs[Bn*Hn*Sn];

__device__ __half g_xh [TOK*Dn];     // x fp16; reused as v_ln fp16 later
__device__ __half g_wqh[Dn*Dn];
__device__ __half g_wkh[Dn*Dn];
__device__ __half g_wvh[Dn*Dn];
__device__ __half g_wsh[Dn*Dn];
__device__ __half g_woh[Dn*Dn];
__device__ __half g_whh[Dn*Dn];
__device__ __half g_wp1h[DFFn*Dn];
__device__ __half g_wp2h[Dn*DFFn];
__device__ __half g_qh [TOK*Dn];    // QKV q out; later attn_out
__device__ __half g_t1h[TOK*Dn];    // QKV k out; later ln1024 h out
__device__ __half g_gh [TOK*Dn];    // QKV v out; later gate g out
__device__ __half g_ffh[TOK*DFFn];
__device__ __half g_qh16[TOK*Dn];   // LN'd q (band input)
__device__ __half g_kh16[TOK*Dn];   // LN'd k (band input)

// ---------------- helpers ----------------
__device__ __forceinline__ void mma_16816(float* c, const uint32_t* a, const uint32_t* b){
    asm volatile(
        "mma.sync.aligned.m16n8k16.row.col.f32.f16.f16.f32 "
        "{%0,%1,%2,%3}, {%4,%5,%6,%7}, {%8,%9}, {%0,%1,%2,%3};"
        : "+f"(c[0]), "+f"(c[1]), "+f"(c[2]), "+f"(c[3])
        : "r"(a[0]), "r"(a[1]), "r"(a[2]), "r"(a[3]), "r"(b[0]), "r"(b[1]));
}
__device__ __forceinline__ void cpa16(void* dst, const void* src){
    uint32_t d = (uint32_t)__cvta_generic_to_shared(dst);
    asm volatile("cp.async.ca.shared.global [%0], [%1], 16;" :: "r"(d), "l"(src));
}
#define CP_COMMIT() asm volatile("cp.async.commit_group;" ::: "memory")
#define CP_WAIT(N)  asm volatile("cp.async.wait_group %0;" :: "n"(N) : "memory")

// ---------------- batched fp32 -> fp16 conversion + colsum init ----------------
struct CV10 { const float* s[9]; __half* d[9]; int n[9]; float* cs; int ncs; };
__global__ void conv_f2h(CV10 cb)
{
    const int m = blockIdx.y;
    int i = (blockIdx.x * 256 + threadIdx.x) * 4;
    if (m == 9){
        if (i < cb.ncs){
            float4 u = { 1.f/1024.f, 1.f/1024.f, 1.f/1024.f, 1.f/1024.f };
            *(float4*)(cb.cs + i) = u;
        }
        return;
    }
    const float* s = cb.s[m];
    __half* d = cb.d[m];
    if (i < cb.n[m]){
        float4 v = *(const float4*)(s + i);
        __half2 h0 = __floats2half2_rn(v.x, v.y);
        __half2 h1 = __floats2half2_rn(v.z, v.w);
        uint2 u = { *(uint32_t*)&h0, *(uint32_t*)&h1 };
        *(uint2*)(d + i) = u;
    }
}

// batch descriptor (kernel param by value; blockIdx.z selects)
struct GB {
    const __half* W[4];
    float*        C[4];
    __half*       Ch[4];
    const float*  bias[4];
};

// ---------------- fp16 mma.sync GEMM (m16n8k16, BK=64, cp.async 3-stage) ---------
// C[M,N] = A[M,K] @ W[N,K]^T (+bias)(+relu); A, W fp16; accum fp32.
// Block 256 thr (8 warps, 2x4), warp tile 64x32, BK=64 (4 k16 chunks / barrier),
// dynamic smem half[3][128][72] x2 (bank-bijective .b32 frag loads). flags bit0=relu.
__global__ void __launch_bounds__(256, 2)
gemm_h(const __half* __restrict__ A, GB gb,
       int K, int lda, int ldb, int ldc, int flags)
{
    extern __shared__ __half sm[];
    __half (*As)[128][72] = (__half(*)[128][72])sm;
    __half (*Bs)[128][72] = (__half(*)[128][72])(sm + 3 * 128 * 72);

    const __half* W    = gb.W[blockIdx.z];
    float*        C    = gb.C[blockIdx.z];
    __half*       Ch   = gb.Ch[blockIdx.z];
    const float*  bias = gb.bias[blockIdx.z];

    const int tid = threadIdx.x, lane = tid & 31, wid = tid >> 5;
    const int wm = wid & 1, wn = wid >> 1;          // warp grid 2 x 4
    const int ml = lane >> 2, cl = lane & 3;

    const int r0 = tid >> 1;                // tile row 0..127
    const int kh = (tid & 1) * 32;          // k half-chunk 0 or 32 (halves)
    const __half* Ap = A + ((size_t)blockIdx.y * 128 + r0) * lda + kh;
    const __half* Wp = W + ((size_t)blockIdx.x * 128 + r0) * ldb + kh;

    float acc[4][4][4];
#pragma unroll
    for (int i = 0; i < 4; i++)
#pragma unroll
        for (int j = 0; j < 4; j++)
#pragma unroll
            for (int r = 0; r < 4; r++) acc[i][j][r] = 0.f;

    const int T = K >> 6;

#define ISSUE(t, s) do { \
    const __half* a_ = Ap + (size_t)(t) * 64; \
    const __half* w_ = Wp + (size_t)(t) * 64; \
    cpa16(&As[s][r0][kh],      a_);       cpa16(&As[s][r0][kh + 8],  a_ + 8); \
    cpa16(&As[s][r0][kh + 16], a_ + 16);  cpa16(&As[s][r0][kh + 24], a_ + 24); \
    cpa16(&Bs[s][r0][kh],      w_);       cpa16(&Bs[s][r0][kh + 8],  w_ + 8); \
    cpa16(&Bs[s][r0][kh + 16], w_ + 16);  cpa16(&Bs[s][r0][kh + 24], w_ + 24); \
    CP_COMMIT(); \
} while(0)

    ISSUE(0, 0);
    ISSUE(1, 1);

#pragma unroll 1
    for (int t = 0; t < T; t++){
        const int s = t % 3;
        if (t + 1 < T) { CP_WAIT(1); } else { CP_WAIT(0); }
        __syncthreads();

        const uint32_t* Au = (const uint32_t*)As[s];   // 36 u32 per row
        const uint32_t* Bu = (const uint32_t*)Bs[s];
#pragma unroll
        for (int kk = 0; kk < 4; kk++){
            uint32_t af[4][4], bf[4][2];
#pragma unroll
            for (int mt = 0; mt < 4; mt++){
                const int m = wm * 64 + mt * 16 + ml;
                af[mt][0] = Au[m * 36 + kk * 8 + cl];
                af[mt][1] = Au[(m + 8) * 36 + kk * 8 + cl];
                af[mt][2] = Au[m * 36 + kk * 8 + cl + 4];
                af[mt][3] = Au[(m + 8) * 36 + kk * 8 + cl + 4];
            }
#pragma unroll
            for (int nt = 0; nt < 4; nt++){
                const int n = wn * 32 + nt * 8 + ml;
                bf[nt][0] = Bu[n * 36 + kk * 8 + cl];
                bf[nt][1] = Bu[n * 36 + kk * 8 + cl + 4];
            }
#pragma unroll
            for (int mt = 0; mt < 4; mt++)
#pragma unroll
                for (int nt = 0; nt < 4; nt++)
                    mma_16816(acc[mt][nt], af[mt], bf[nt]);
        }

        if (t + 2 < T) ISSUE(t + 2, (t + 2) % 3);
    }
#undef ISSUE

    // epilogue
    const int rbase = blockIdx.y * 128 + wm * 64 + ml;
    const int cbase = blockIdx.x * 128 + wn * 32 + 2 * cl;
#pragma unroll
    for (int mt = 0; mt < 4; mt++){
#pragma unroll
        for (int nt = 0; nt < 4; nt++){
            const int row = rbase + mt * 16;
            const int col = cbase + nt * 8;
            float bx0 = 0.f, bx1 = 0.f;
            if (bias){ bx0 = bias[col]; bx1 = bias[col + 1]; }
            float v00 = acc[mt][nt][0] + bx0, v01 = acc[mt][nt][1] + bx1;
            float v10 = acc[mt][nt][2] + bx0, v11 = acc[mt][nt][3] + bx1;
            if (flags & 1){
                v00 = fmaxf(v00, 0.f); v01 = fmaxf(v01, 0.f);
                v10 = fmaxf(v10, 0.f); v11 = fmaxf(v11, 0.f);
            }
            if (C){
                float2 u0 = { v00, v01 }, u1 = { v10, v11 };
                *(float2*)&C[(size_t)row * ldc + col] = u0;
                *(float2*)&C[(size_t)(row + 8) * ldc + col] = u1;
            }
            if (Ch){
                __half2 h0 = __floats2half2_rn(v00, v01);
                __half2 h1 = __floats2half2_rn(v10, v11);
                *(__half2*)&Ch[(size_t)row * ldc + col] = h0;
                *(__half2*)&Ch[(size_t)(row + 8) * ldc + col] = h1;
            }
        }
    }
}
#define GEMM_SMEM (3 * 128 * 72 * 2 * 2)   // 110592 B dynamic

// ---------------- per-head layernorm over DH=64 (fp16 in, fp16 out) ---------------
struct LNBH { const __half* in[3]; __half* out[3]; };
__global__ void ln_head_kernel(LNBH bufs,
                               const float* __restrict__ g, const float* __restrict__ b)
{
    int row = blockIdx.x * 8 + (threadIdx.x >> 5);
    int lane = threadIdx.x & 31;
    const __half* p = bufs.in[blockIdx.y] + (size_t)row * 64;
    __half* ph = bufs.out[blockIdx.y] + (size_t)row * 64;
    float v0 = __half2float(p[lane]), v1 = __half2float(p[lane + 32]);
    float s = v0 + v1;
#pragma unroll
    for (int off = 16; off; off >>= 1) s += __shfl_xor_sync(0xffffffffu, s, off);
    float mu = s * (1.f / 64.f);
    float d0 = v0 - mu, d1 = v1 - mu;
    float q = d0 * d0 + d1 * d1;
#pragma unroll
    for (int off = 16; off; off >>= 1) q += __shfl_xor_sync(0xffffffffu, q, off);
    float r = rsqrtf(q * (1.f / 64.f) + EPSF);
    ph[lane]      = __float2half(d0 * r * g[lane]      + b[lane]);
    ph[lane + 32] = __float2half(d1 * r * g[lane + 32] + b[lane + 32]);
}

// ---------------- block reduction helper ----------------
__device__ __forceinline__ float2 blockReduce2(float a, float b)
{
    __shared__ float sa[8], sb[8];
    int lane = threadIdx.x & 31, w = threadIdx.x >> 5;
#pragma unroll
    for (int off = 16; off; off >>= 1) {
        a += __shfl_xor_sync(0xffffffffu, a, off);
        b += __shfl_xor_sync(0xffffffffu, b, off);
    }
    __syncthreads();
    if (lane == 0) { sa[w] = a; sb[w] = b; }
    __syncthreads();
    float ra = 0.f, rb = 0.f;
#pragma unroll
    for (int i = 0; i < 8; i++) { ra += sa[i]; rb += sb[i]; }
    return make_float2(ra, rb);
}

// ---------------- layernorm over D=1024 (+optional residual, +optional half out) --
__global__ void ln1024_kernel(const float* __restrict__ in, const float* __restrict__ res,
                              const float* __restrict__ g, const float* __restrict__ b,
                              float* __restrict__ out, __half* __restrict__ outh)
{
    int row = blockIdx.x, tid = threadIdx.x;
    size_t base = (size_t)row * 1024 + tid * 4;
    float4 v = *(const float4*)(in + base);
    float x[4] = { v.x, v.y, v.z, v.w };
    if (res) {
        float4 rv = *(const float4*)(res + base);
        x[0] += rv.x; x[1] += rv.y; x[2] += rv.z; x[3] += rv.w;
    }
    float sa = 0.f, sb = 0.f;
#pragma unroll
    for (int i = 0; i < 4; i++) { sa += x[i]; sb += x[i] * x[i]; }
    float2 r = blockReduce2(sa, sb);
    float mu = r.x * (1.f / 1024.f);
    float var = r.y * (1.f / 1024.f) - mu * mu;
    float rs = rsqrtf(var + EPSF);
    float4 g4 = *(const float4*)(g + tid * 4);
    float4 b4 = *(const float4*)(b + tid * 4);
    float4 o;
    o.x = (x[0] - mu) * rs * g4.x + b4.x;
    o.y = (x[1] - mu) * rs * g4.y + b4.y;
    o.z = (x[2] - mu) * rs * g4.z + b4.z;
    o.w = (x[3] - mu) * rs * g4.w + b4.w;
    *(float4*)(out + base) = o;
    if (outh){
        __half2 h0 = __floats2half2_rn(o.x, o.y);
        __half2 h1 = __floats2half2_rn(o.z, o.w);
        uint2 u = { *(uint32_t*)&h0, *(uint32_t*)&h1 };
        *(uint2*)(outh + base) = u;
    }
}

// ---------------- fused gate (fp32 g out + fp16 g out) ----------------------------
__global__ void gate_kernel(const float* __restrict__ sp, const float* __restrict__ hp,
                            const float* __restrict__ bf,
                            const float* __restrict__ gg, const float* __restrict__ gb,
                            float* __restrict__ out, __half* __restrict__ outh)
{
    int row = blockIdx.x, tid = threadIdx.x;
    size_t base = (size_t)row * 1024 + tid * 4;
    float4 sv = *(const float4*)(sp + base);
    float4 hv = *(const float4*)(hp + base);
    float s[4] = { sv.x, sv.y, sv.z, sv.w };
    float h[4] = { hv.x, hv.y, hv.z, hv.w };

    float sa = 0.f, sb = 0.f;
#pragma unroll
    for (int i = 0; i < 4; i++) { sa += s[i]; sb += s[i] * s[i]; }
    float2 r = blockReduce2(sa, sb);
    float mus = r.x * (1.f / 1024.f);
    float rs = rsqrtf(r.y * (1.f / 1024.f) - mus * mus + EPSF);

    sa = 0.f; sb = 0.f;
#pragma unroll
    for (int i = 0; i < 4; i++) { sa += h[i]; sb += h[i] * h[i]; }
    r = blockReduce2(sa, sb);
    float muh = r.x * (1.f / 1024.f);
    float rh = rsqrtf(r.y * (1.f / 1024.f) - muh * muh + EPSF);

    float4 g4 = *(const float4*)(gg + tid * 4);
    float4 b4 = *(const float4*)(gb + tid * 4);
    float4 f4 = *(const float4*)(bf + tid * 4);
    float gA[4] = { g4.x, g4.y, g4.z, g4.w };
    float bA[4] = { b4.x, b4.y, b4.z, b4.w };
    float fA[4] = { f4.x, f4.y, f4.z, f4.w };

    float t[4];
    sa = 0.f; sb = 0.f;
#pragma unroll
    for (int i = 0; i < 4; i++) {
        float sf = (s[i] - mus) * rs * gA[i] + bA[i];
        float hf = (h[i] - muh) * rh * gA[i] + bA[i];
        float f = 1.f / (1.f + expf(-(sf + hf + fA[i])));
        float ti = f * sf + (1.f - f) * hf;
        t[i] = ti; sa += ti; sb += ti * ti;
    }
    r = blockReduce2(sa, sb);
    float mut = r.x * (1.f / 1024.f);
    float rt = rsqrtf(r.y * (1.f / 1024.f) - mut * mut + EPSF);
    float4 o;
    o.x = (t[0] - mut) * rt * gA[0] + bA[0];
    o.y = (t[1] - mut) * rt * gA[1] + bA[1];
    o.z = (t[2] - mut) * rt * gA[2] + bA[2];
    o.w = (t[3] - mut) * rt * gA[3] + bA[3];
    *(float4*)(out + base) = o;
    __half2 h0 = __floats2half2_rn(o.x, o.y);
    __half2 h1 = __floats2half2_rn(o.z, o.w);
    uint2 u = { *(uint32_t*)&h0, *(uint32_t*)&h1 };
    *(uint2*)(outh + base) = u;
}

// ---------------- banded attention colsum via fp16 MMA ---------------------------
__global__ void __launch_bounds__(256)
attn_mma(const __half* __restrict__ qh, const __half* __restrict__ kh,
         float* __restrict__ colsum)
{
    __shared__ __half Qs[32][72];
    __shared__ __half Ks[128][72];
    __shared__ float csm[128];
    __shared__ float pmax[32][4];
    __shared__ float psum[32][4];

    const int tid = threadIdx.x, lane = tid & 31, wid = tid >> 5;
    const int wm = wid & 1, wn = wid >> 1;      // warp grid 2(m) x 4(n)
    const int ml = lane >> 2, cl = lane & 3;
    const int nb = blockIdx.z, hh = blockIdx.y;
    const int qb0 = blockIdx.x * 32;
    const int kb0 = qb0 - 96;

    if (tid < 128) csm[tid] = 0.f;

    {
        int row = tid >> 3, seg = tid & 7;
        const __half* src = qh + (((size_t)nb * Sn + qb0 + row) * Hn + hh) * 64 + seg * 8;
        cpa16(&Qs[row][seg * 8], src);
    }
#pragma unroll
    for (int i = 0; i < 4; i++){
        int idx = tid + i * 256;
        int row = idx >> 3, seg = idx & 7;
        int kg = kb0 + row;
        if (kg >= 0){
            const __half* src = kh + (((size_t)nb * Sn + kg) * Hn + hh) * 64 + seg * 8;
            cpa16(&Ks[row][seg * 8], src);
        } else {
            uint4 z = {0u, 0u, 0u, 0u};
            *(uint4*)&Ks[row][seg * 8] = z;
        }
    }
    CP_COMMIT();
    CP_WAIT(0);
    __syncthreads();

    const uint32_t* Qu = (const uint32_t*)Qs;    // 36 u32 per row
    const uint32_t* Ku = (const uint32_t*)Ks;

    float c[4][4];
#pragma unroll
    for (int nt = 0; nt < 4; nt++)
#pragma unroll
        for (int j = 0; j < 4; j++) c[nt][j] = 0.f;

    const int m = wm * 16 + ml;
#pragma unroll
    for (int kk = 0; kk < 4; kk++){
        uint32_t af[4], bf[4][2];
        af[0] = Qu[m * 36 + kk * 8 + cl];
        af[1] = Qu[(m + 8) * 36 + kk * 8 + cl];
        af[2] = Qu[m * 36 + kk * 8 + cl + 4];
        af[3] = Qu[(m + 8) * 36 + kk * 8 + cl + 4];
#pragma unroll
        for (int nt = 0; nt < 4; nt++){
            const int n = wn * 32 + nt * 8 + ml;
            bf[nt][0] = Ku[n * 36 + kk * 8 + cl];
            bf[nt][1] = Ku[n * 36 + kk * 8 + cl + 4];
        }
#pragma unroll
        for (int nt = 0; nt < 4; nt++)
            mma_16816(c[nt], af, bf[nt]);
    }

    const int r_lo = wm * 16 + ml, r_hi = r_lo + 8;
    float lg[4][4];
    float mx_lo = -3.4e38f, mx_hi = -3.4e38f;
#pragma unroll
    for (int nt = 0; nt < 4; nt++){
#pragma unroll
        for (int j = 0; j < 4; j++){
            int col = wn * 32 + nt * 8 + 2 * cl + (j & 1);
            int row = (j < 2) ? r_lo : r_hi;
            int qg = qb0 + row, kg = kb0 + col;
            bool valid = (qg >= 1) && (kg >= 0) && (col >= row) && (col < row + 96);
            float v = valid ? c[nt][j] * 0.03125f - (float)(96 + row - col) : -3.4e38f;
            lg[nt][j] = v;
            if (j < 2) mx_lo = fmaxf(mx_lo, v); else mx_hi = fmaxf(mx_hi, v);
        }
    }
    mx_lo = fmaxf(mx_lo, __shfl_xor_sync(0xffffffffu, mx_lo, 1));
    mx_lo = fmaxf(mx_lo, __shfl_xor_sync(0xffffffffu, mx_lo, 2));
    mx_hi = fmaxf(mx_hi, __shfl_xor_sync(0xffffffffu, mx_hi, 1));
    mx_hi = fmaxf(mx_hi, __shfl_xor_sync(0xffffffffu, mx_hi, 2));
    if (cl == 0){ pmax[r_lo][wn] = mx_lo; pmax[r_hi][wn] = mx_hi; }
    __syncthreads();
    float rm_lo = fmaxf(fmaxf(pmax[r_lo][0], pmax[r_lo][1]),
                        fmaxf(pmax[r_lo][2], pmax[r_lo][3]));
    float rm_hi = fmaxf(fmaxf(pmax[r_hi][0], pmax[r_hi][1]),
                        fmaxf(pmax[r_hi][2], pmax[r_hi][3]));

    float p[4][4];
    float s_lo = 0.f, s_hi = 0.f;
#pragma unroll
    for (int nt = 0; nt < 4; nt++){
#pragma unroll
        for (int j = 0; j < 4; j++){
            float v = lg[nt][j];
            float e = (v > -1e30f) ? expf(v - ((j < 2) ? rm_lo : rm_hi)) : 0.f;
            p[nt][j] = e;
            if (j < 2) s_lo += e; else s_hi += e;
        }
    }
    s_lo += __shfl_xor_sync(0xffffffffu, s_lo, 1);
    s_lo += __shfl_xor_sync(0xffffffffu, s_lo, 2);
    s_hi += __shfl_xor_sync(0xffffffffu, s_hi, 1);
    s_hi += __shfl_xor_sync(0xffffffffu, s_hi, 2);
    if (cl == 0){ psum[r_lo][wn] = s_lo; psum[r_hi][wn] = s_hi; }
    __syncthreads();
    float Z_lo = psum[r_lo][0] + psum[r_lo][1] + psum[r_lo][2] + psum[r_lo][3];
    float Z_hi = psum[r_hi][0] + psum[r_hi][1] + psum[r_hi][2] + psum[r_hi][3];
    float iz_lo = (Z_lo > 0.f) ? 1.f / Z_lo : 0.f;
    float iz_hi = (Z_hi > 0.f) ? 1.f / Z_hi : 0.f;

#pragma unroll
    for (int nt = 0; nt < 4; nt++){
#pragma unroll
        for (int j = 0; j < 4; j++){
            float val = p[nt][j] * ((j < 2) ? iz_lo : iz_hi);
            if (val != 0.f){
                int col = wn * 32 + nt * 8 + 2 * cl + (j & 1);
                atomicAdd(&csm[col], val);
            }
        }
    }
    __syncthreads();

    float* dst = colsum + (size_t)(nb * Hn + hh) * Sn;
    for (int i = tid; i < 128; i += 256){
        int kg = kb0 + i;
        if (kg >= 0 && csm[i] != 0.f) atomicAdd(&dst[kg], csm[i]);
    }
}

// ---------------- elementwise: attn_out (fp16) = v_ln(fp16) * colsum --------------
__global__ void scale_v_kernel(const __half* __restrict__ vln, const float* __restrict__ colsum,
                               __half* __restrict__ out)
{
    int idx = blockIdx.x * blockDim.x + threadIdx.x;
    int token = idx >> 10;
    int n = token >> 10;
    int sidx = token & 1023;
    int h = (idx >> 6) & 15;
    out[idx] = __float2half(__half2float(vln[idx]) *
                            colsum[(((size_t)n * Hn + h) << 10) + sidx]);
}

// ---------------- host orchestration ----------------
extern "C" void kernel_launch(void* const* d_in, const int* in_sizes, int n_in,
                              void* d_out, int out_size)
{
    const float* x     = (const float*)d_in[0];
    const float* Wq    = (const float*)d_in[2];
    const float* Wk    = (const float*)d_in[3];
    const float* Wv    = (const float*)d_in[4];
    const float* ln1g  = (const float*)d_in[5];
    const float* ln1b  = (const float*)d_in[6];
    const float* Wo    = (const float*)d_in[7];
    const float* bo    = (const float*)d_in[8];
    const float* ln2g  = (const float*)d_in[9];
    const float* ln2b  = (const float*)d_in[10];
    const float* Ws    = (const float*)d_in[11];
    const float* Wh    = (const float*)d_in[12];
    const float* bf    = (const float*)d_in[13];
    const float* lnfgg = (const float*)d_in[14];
    const float* lnfgb = (const float*)d_in[15];
    const float* Wp1   = (const float*)d_in[16];
    const float* bp1   = (const float*)d_in[17];
    const float* Wp2   = (const float*)d_in[18];
    const float* bp2   = (const float*)d_in[19];
    const float* lnffg = (const float*)d_in[20];
    const float* lnffb = (const float*)d_in[21];
    float* out = (float*)d_out;

    float *gq, *t1, *t2, *t3, *cs;
    __half *xh, *wqh, *wkh, *wvh, *wsh, *woh, *whh, *wp1h, *wp2h;
    __half *qh, *t1h, *gh, *ffh, *qh16, *kh16;
    cudaGetSymbolAddress((void**)&gq, g_q);
    cudaGetSymbolAddress((void**)&t1, g_t1);
    cudaGetSymbolAddress((void**)&t2, g_t2);
    cudaGetSymbolAddress((void**)&t3, g_t3);
    cudaGetSymbolAddress((void**)&cs, g_cs);
    cudaGetSymbolAddress((void**)&xh,  g_xh);
    cudaGetSymbolAddress((void**)&wqh, g_wqh);
    cudaGetSymbolAddress((void**)&wkh, g_wkh);
    cudaGetSymbolAddress((void**)&wvh, g_wvh);
    cudaGetSymbolAddress((void**)&wsh, g_wsh);
    cudaGetSymbolAddress((void**)&woh, g_woh);
    cudaGetSymbolAddress((void**)&whh, g_whh);
    cudaGetSymbolAddress((void**)&wp1h, g_wp1h);
    cudaGetSymbolAddress((void**)&wp2h, g_wp2h);
    cudaGetSymbolAddress((void**)&qh,  g_qh);
    cudaGetSymbolAddress((void**)&t1h, g_t1h);
    cudaGetSymbolAddress((void**)&gh,  g_gh);
    cudaGetSymbolAddress((void**)&ffh, g_ffh);
    cudaGetSymbolAddress((void**)&qh16, g_qh16);
    cudaGetSymbolAddress((void**)&kh16, g_kh16);
    __half* vh16 = xh;   // xh dead after QKV/Ws GEMM; reuse for v_ln fp16

    cudaFuncSetAttribute(gemm_h, cudaFuncAttributeMaxDynamicSharedMemorySize, GEMM_SMEM);

    // convert x + all weights to fp16; slice 9 initializes colsum to 1/1024
    {
        CV10 cb;
        cb.s[0]=x;   cb.d[0]=xh;   cb.n[0]=TOK*Dn;
        cb.s[1]=Wq;  cb.d[1]=wqh;  cb.n[1]=Dn*Dn;
        cb.s[2]=Wk;  cb.d[2]=wkh;  cb.n[2]=Dn*Dn;
        cb.s[3]=Wv;  cb.d[3]=wvh;  cb.n[3]=Dn*Dn;
        cb.s[4]=Ws;  cb.d[4]=wsh;  cb.n[4]=Dn*Dn;
        cb.s[5]=Wo;  cb.d[5]=woh;  cb.n[5]=Dn*Dn;
        cb.s[6]=Wh;  cb.d[6]=whh;  cb.n[6]=Dn*Dn;
        cb.s[7]=Wp1; cb.d[7]=wp1h; cb.n[7]=DFFn*Dn;
        cb.s[8]=Wp2; cb.d[8]=wp2h; cb.n[8]=Dn*DFFn;
        cb.cs = cs; cb.ncs = Bn*Hn*Sn;
        conv_f2h<<<dim3(DFFn*Dn/4/256, 10), 256>>>(cb);
    }

    // QKV + Ws projections in one batched launch (A = xh)
    // q,k,v -> fp16-only scratch (qh, t1h, gh); Ws -> t2 fp32 (gate input)
    {
        GB gb;
        gb.W[0] = wqh; gb.W[1] = wkh; gb.W[2] = wvh; gb.W[3] = wsh;
        gb.C[0] = nullptr; gb.C[1] = nullptr; gb.C[2] = nullptr; gb.C[3] = t2;
        gb.Ch[0] = qh; gb.Ch[1] = t1h; gb.Ch[2] = gh; gb.Ch[3] = nullptr;
        gb.bias[0] = gb.bias[1] = gb.bias[2] = gb.bias[3] = nullptr;
        gemm_h<<<dim3(8, 32, 4), 256, GEMM_SMEM>>>(xh, gb, Dn, Dn, Dn, Dn, 0);
    }

    // per-head LN: q,k,v fp16 -> fp16 LN'd buffers
    {
        LNBH b3;
        b3.in[0] = qh;   b3.in[1] = t1h;  b3.in[2] = gh;
        b3.out[0] = qh16; b3.out[1] = kh16; b3.out[2] = vh16;
        ln_head_kernel<<<dim3(TOK * Hn / 8, 3), 256>>>(b3, ln1g, ln1b);
    }

    // banded attention colsum (MMA path); colsum pre-initialized by conv slice 9
    attn_mma<<<dim3(Sn / 32, Hn, Bn), 256>>>(qh16, kh16, cs);

    // attn_out (fp16) = v_ln * colsum  (qh reused after ln_head consumed it)
    scale_v_kernel<<<(TOK * Dn) / 256, 256>>>(vh16, cs, qh);

    // output projection + LN -> h (t1 fp32 + t1h fp16)
    {
        GB gb; gb.W[0] = woh; gb.C[0] = t1; gb.Ch[0] = nullptr; gb.bias[0] = bo;
        gemm_h<<<dim3(8, 32, 1), 256, GEMM_SMEM>>>(qh, gb, Dn, Dn, Dn, Dn, 0);
    }
    ln1024_kernel<<<TOK, 256>>>(t1, nullptr, ln2g, ln2b, t1, t1h);

    // fusion gate (t2 = x@Ws^T computed above)
    {
        GB gb; gb.W[0] = whh; gb.C[0] = t3; gb.Ch[0] = nullptr; gb.bias[0] = nullptr;
        gemm_h<<<dim3(8, 32, 1), 256, GEMM_SMEM>>>(t1h, gb, Dn, Dn, Dn, Dn, 0);
    }
    gate_kernel<<<TOK, 256>>>(t2, t3, bf, lnfgg, lnfgb, gq, gh);  // g fp32 -> gq, fp16 -> gh

    // FFN (FFN1 writes fp16 only; FFN2 fp32)
    {
        GB gb; gb.W[0] = wp1h; gb.C[0] = nullptr; gb.Ch[0] = ffh; gb.bias[0] = bp1;
        gemm_h<<<dim3(32, 32, 1), 256, GEMM_SMEM>>>(gh, gb, Dn, Dn, Dn, DFFn, 1);
    }
    {
        GB gb; gb.W[0] = wp2h; gb.C[0] = t3; gb.Ch[0] = nullptr; gb.bias[0] = bp2;
        gemm_h<<<dim3(8, 32, 1), 256, GEMM_SMEM>>>(ffh, gb, DFFn, DFFn, DFFn, Dn, 0);
    }

    // final residual + LN
    ln1024_kernel<<<TOK, 256>>>(t3, gq, lnffg, lnffb, out, nullptr);
}

// round 13
// speedup vs baseline: 1.0289x; 1.0289x over previous
#include <cuda_runtime.h>
#include <cuda_fp16.h>
#include <math.h>
#include <stdint.h>

// Problem constants
#define Bn   4
#define Sn   1024
#define Dn   1024
#define Hn   16
#define DHn  64
#define DFFn 4096
#define TOK  (Bn*Sn)          // 4096
#define EPSF 1e-5f
#define NEGF (-1e20f)

// ---------------- static device workspaces ----------------
__device__ float g_q [TOK*Dn];     // gate g fp32 target
__device__ float g_t1[TOK*Dn];
__device__ float g_t2[TOK*Dn];
__device__ float g_t3[TOK*Dn];
__device__ float g_cs[Bn*Hn*Sn];

__device__ __half g_xh [TOK*Dn];     // x fp16; reused as v_ln fp16 later
__device__ __half g_wqh[Dn*Dn];
__device__ __half g_wkh[Dn*Dn];
__device__ __half g_wvh[Dn*Dn];
__device__ __half g_wsh[Dn*Dn];
__device__ __half g_woh[Dn*Dn];
__device__ __half g_whh[Dn*Dn];
__device__ __half g_wp1h[DFFn*Dn];
__device__ __half g_wp2h[Dn*DFFn];
__device__ __half g_qh [TOK*Dn];    // QKV q out; later attn_out
__device__ __half g_t1h[TOK*Dn];    // QKV k out; later ln1024 h out
__device__ __half g_gh [TOK*Dn];    // QKV v out; later gate g out
__device__ __half g_ffh[TOK*DFFn];
__device__ __half g_qh16[TOK*Dn];   // LN'd q (band input)
__device__ __half g_kh16[TOK*Dn];   // LN'd k (band input)

// ---------------- helpers ----------------
__device__ __forceinline__ void mma_16816(float* c, const uint32_t* a, const uint32_t* b){
    asm volatile(
        "mma.sync.aligned.m16n8k16.row.col.f32.f16.f16.f32 "
        "{%0,%1,%2,%3}, {%4,%5,%6,%7}, {%8,%9}, {%0,%1,%2,%3};"
        : "+f"(c[0]), "+f"(c[1]), "+f"(c[2]), "+f"(c[3])
        : "r"(a[0]), "r"(a[1]), "r"(a[2]), "r"(a[3]), "r"(b[0]), "r"(b[1]));
}
__device__ __forceinline__ void cpa16(void* dst, const void* src){
    uint32_t d = (uint32_t)__cvta_generic_to_shared(dst);
    asm volatile("cp.async.ca.shared.global [%0], [%1], 16;" :: "r"(d), "l"(src));
}
#define CP_COMMIT() asm volatile("cp.async.commit_group;" ::: "memory")
#define CP_WAIT(N)  asm volatile("cp.async.wait_group %0;" :: "n"(N) : "memory")

// ---------------- batched fp32 -> fp16 conversion + colsum init ----------------
struct CV10 { const float* s[9]; __half* d[9]; int n[9]; float* cs; int ncs; };
__global__ void conv_f2h(CV10 cb)
{
    const int m = blockIdx.y;
    int i = (blockIdx.x * 256 + threadIdx.x) * 4;
    if (m == 9){
        if (i < cb.ncs){
            float4 u = { 1.f/1024.f, 1.f/1024.f, 1.f/1024.f, 1.f/1024.f };
            *(float4*)(cb.cs + i) = u;
        }
        return;
    }
    const float* s = cb.s[m];
    __half* d = cb.d[m];
    if (i < cb.n[m]){
        float4 v = *(const float4*)(s + i);
        __half2 h0 = __floats2half2_rn(v.x, v.y);
        __half2 h1 = __floats2half2_rn(v.z, v.w);
        uint2 u = { *(uint32_t*)&h0, *(uint32_t*)&h1 };
        *(uint2*)(d + i) = u;
    }
}

// batch descriptor (kernel param by value; blockIdx.z selects)
struct GB {
    const __half* W[4];
    float*        C[4];
    __half*       Ch[4];
    const float*  bias[4];
};

// ---------------- fp16 mma.sync GEMM (m16n8k16, BK=32, cp.async 3-stage) ---------
// C[M,N] = A[M,K] @ W[N,K]^T (+bias)(+relu); A, W fp16; accum fp32.
// Block 256 thr (8 warps, 2x4), warp tile 64x32, BK=32 (2 k16 chunks / barrier),
// dynamic smem half[3][128][40] x2 (bank-bijective .b32 frag loads). flags bit0=relu.
__global__ void __launch_bounds__(256, 2)
gemm_h(const __half* __restrict__ A, GB gb,
       int K, int lda, int ldb, int ldc, int flags)
{
    extern __shared__ __half sm[];
    __half (*As)[128][40] = (__half(*)[128][40])sm;
    __half (*Bs)[128][40] = (__half(*)[128][40])(sm + 3 * 128 * 40);

    const __half* W    = gb.W[blockIdx.z];
    float*        C    = gb.C[blockIdx.z];
    __half*       Ch   = gb.Ch[blockIdx.z];
    const float*  bias = gb.bias[blockIdx.z];

    const int tid = threadIdx.x, lane = tid & 31, wid = tid >> 5;
    const int wm = wid & 1, wn = wid >> 1;          // warp grid 2 x 4
    const int ml = lane >> 2, cl = lane & 3;

    const int r0 = tid >> 1;                // tile row 0..127
    const int kh = (tid & 1) * 16;          // k half-chunk 0 or 16 (halves)
    const __half* Ap = A + ((size_t)blockIdx.y * 128 + r0) * lda + kh;
    const __half* Wp = W + ((size_t)blockIdx.x * 128 + r0) * ldb + kh;

    float acc[4][4][4];
#pragma unroll
    for (int i = 0; i < 4; i++)
#pragma unroll
        for (int j = 0; j < 4; j++)
#pragma unroll
            for (int r = 0; r < 4; r++) acc[i][j][r] = 0.f;

    const int T = K >> 5;

#define ISSUE(t, s) do { \
    const __half* a_ = Ap + (size_t)(t) * 32; \
    const __half* w_ = Wp + (size_t)(t) * 32; \
    cpa16(&As[s][r0][kh],     a_);  cpa16(&As[s][r0][kh + 8], a_ + 8); \
    cpa16(&Bs[s][r0][kh],     w_);  cpa16(&Bs[s][r0][kh + 8], w_ + 8); \
    CP_COMMIT(); \
} while(0)

    ISSUE(0, 0);
    ISSUE(1, 1);

#pragma unroll 1
    for (int t = 0; t < T; t++){
        const int s = t % 3;
        if (t + 1 < T) { CP_WAIT(1); } else { CP_WAIT(0); }
        __syncthreads();

        const uint32_t* Au = (const uint32_t*)As[s];   // 20 u32 per row
        const uint32_t* Bu = (const uint32_t*)Bs[s];
#pragma unroll
        for (int kk = 0; kk < 2; kk++){
            uint32_t af[4][4], bf[4][2];
#pragma unroll
            for (int mt = 0; mt < 4; mt++){
                const int m = wm * 64 + mt * 16 + ml;
                af[mt][0] = Au[m * 20 + kk * 8 + cl];
                af[mt][1] = Au[(m + 8) * 20 + kk * 8 + cl];
                af[mt][2] = Au[m * 20 + kk * 8 + cl + 4];
                af[mt][3] = Au[(m + 8) * 20 + kk * 8 + cl + 4];
            }
#pragma unroll
            for (int nt = 0; nt < 4; nt++){
                const int n = wn * 32 + nt * 8 + ml;
                bf[nt][0] = Bu[n * 20 + kk * 8 + cl];
                bf[nt][1] = Bu[n * 20 + kk * 8 + cl + 4];
            }
#pragma unroll
            for (int mt = 0; mt < 4; mt++)
#pragma unroll
                for (int nt = 0; nt < 4; nt++)
                    mma_16816(acc[mt][nt], af[mt], bf[nt]);
        }

        if (t + 2 < T) ISSUE(t + 2, (t + 2) % 3);
    }
#undef ISSUE

    // epilogue
    const int rbase = blockIdx.y * 128 + wm * 64 + ml;
    const int cbase = blockIdx.x * 128 + wn * 32 + 2 * cl;
#pragma unroll
    for (int mt = 0; mt < 4; mt++){
#pragma unroll
        for (int nt = 0; nt < 4; nt++){
            const int row = rbase + mt * 16;
            const int col = cbase + nt * 8;
            float bx0 = 0.f, bx1 = 0.f;
            if (bias){ bx0 = bias[col]; bx1 = bias[col + 1]; }
            float v00 = acc[mt][nt][0] + bx0, v01 = acc[mt][nt][1] + bx1;
            float v10 = acc[mt][nt][2] + bx0, v11 = acc[mt][nt][3] + bx1;
            if (flags & 1){
                v00 = fmaxf(v00, 0.f); v01 = fmaxf(v01, 0.f);
                v10 = fmaxf(v10, 0.f); v11 = fmaxf(v11, 0.f);
            }
            if (C){
                float2 u0 = { v00, v01 }, u1 = { v10, v11 };
                *(float2*)&C[(size_t)row * ldc + col] = u0;
                *(float2*)&C[(size_t)(row + 8) * ldc + col] = u1;
            }
            if (Ch){
                __half2 h0 = __floats2half2_rn(v00, v01);
                __half2 h1 = __floats2half2_rn(v10, v11);
                *(__half2*)&Ch[(size_t)row * ldc + col] = h0;
                *(__half2*)&Ch[(size_t)(row + 8) * ldc + col] = h1;
            }
        }
    }
}
#define GEMM_SMEM (3 * 128 * 40 * 2 * 2)   // 61440 B dynamic

// ---------------- per-head layernorm over DH=64 (fp16 in, fp16 out) ---------------
struct LNBH { const __half* in[3]; __half* out[3]; };
__global__ void ln_head_kernel(LNBH bufs,
                               const float* __restrict__ g, const float* __restrict__ b)
{
    int row = blockIdx.x * 8 + (threadIdx.x >> 5);
    int lane = threadIdx.x & 31;
    const __half* p = bufs.in[blockIdx.y] + (size_t)row * 64;
    __half* ph = bufs.out[blockIdx.y] + (size_t)row * 64;
    float v0 = __half2float(p[lane]), v1 = __half2float(p[lane + 32]);
    float s = v0 + v1;
#pragma unroll
    for (int off = 16; off; off >>= 1) s += __shfl_xor_sync(0xffffffffu, s, off);
    float mu = s * (1.f / 64.f);
    float d0 = v0 - mu, d1 = v1 - mu;
    float q = d0 * d0 + d1 * d1;
#pragma unroll
    for (int off = 16; off; off >>= 1) q += __shfl_xor_sync(0xffffffffu, q, off);
    float r = rsqrtf(q * (1.f / 64.f) + EPSF);
    ph[lane]      = __float2half(d0 * r * g[lane]      + b[lane]);
    ph[lane + 32] = __float2half(d1 * r * g[lane + 32] + b[lane + 32]);
}

// ---------------- block reduction helper ----------------
__device__ __forceinline__ float2 blockReduce2(float a, float b)
{
    __shared__ float sa[8], sb[8];
    int lane = threadIdx.x & 31, w = threadIdx.x >> 5;
#pragma unroll
    for (int off = 16; off; off >>= 1) {
        a += __shfl_xor_sync(0xffffffffu, a, off);
        b += __shfl_xor_sync(0xffffffffu, b, off);
    }
    __syncthreads();
    if (lane == 0) { sa[w] = a; sb[w] = b; }
    __syncthreads();
    float ra = 0.f, rb = 0.f;
#pragma unroll
    for (int i = 0; i < 8; i++) { ra += sa[i]; rb += sb[i]; }
    return make_float2(ra, rb);
}

// ---------------- layernorm over D=1024 (+optional residual, +optional half out) --
__global__ void ln1024_kernel(const float* __restrict__ in, const float* __restrict__ res,
                              const float* __restrict__ g, const float* __restrict__ b,
                              float* __restrict__ out, __half* __restrict__ outh)
{
    int row = blockIdx.x, tid = threadIdx.x;
    size_t base = (size_t)row * 1024 + tid * 4;
    float4 v = *(const float4*)(in + base);
    float x[4] = { v.x, v.y, v.z, v.w };
    if (res) {
        float4 rv = *(const float4*)(res + base);
        x[0] += rv.x; x[1] += rv.y; x[2] += rv.z; x[3] += rv.w;
    }
    float sa = 0.f, sb = 0.f;
#pragma unroll
    for (int i = 0; i < 4; i++) { sa += x[i]; sb += x[i] * x[i]; }
    float2 r = blockReduce2(sa, sb);
    float mu = r.x * (1.f / 1024.f);
    float var = r.y * (1.f / 1024.f) - mu * mu;
    float rs = rsqrtf(var + EPSF);
    float4 g4 = *(const float4*)(g + tid * 4);
    float4 b4 = *(const float4*)(b + tid * 4);
    float4 o;
    o.x = (x[0] - mu) * rs * g4.x + b4.x;
    o.y = (x[1] - mu) * rs * g4.y + b4.y;
    o.z = (x[2] - mu) * rs * g4.z + b4.z;
    o.w = (x[3] - mu) * rs * g4.w + b4.w;
    *(float4*)(out + base) = o;
    if (outh){
        __half2 h0 = __floats2half2_rn(o.x, o.y);
        __half2 h1 = __floats2half2_rn(o.z, o.w);
        uint2 u = { *(uint32_t*)&h0, *(uint32_t*)&h1 };
        *(uint2*)(outh + base) = u;
    }
}

// ---------------- fused gate (fp32 g out + fp16 g out) ----------------------------
__global__ void gate_kernel(const float* __restrict__ sp, const float* __restrict__ hp,
                            const float* __restrict__ bf,
                            const float* __restrict__ gg, const float* __restrict__ gb,
                            float* __restrict__ out, __half* __restrict__ outh)
{
    int row = blockIdx.x, tid = threadIdx.x;
    size_t base = (size_t)row * 1024 + tid * 4;
    float4 sv = *(const float4*)(sp + base);
    float4 hv = *(const float4*)(hp + base);
    float s[4] = { sv.x, sv.y, sv.z, sv.w };
    float h[4] = { hv.x, hv.y, hv.z, hv.w };

    float sa = 0.f, sb = 0.f;
#pragma unroll
    for (int i = 0; i < 4; i++) { sa += s[i]; sb += s[i] * s[i]; }
    float2 r = blockReduce2(sa, sb);
    float mus = r.x * (1.f / 1024.f);
    float rs = rsqrtf(r.y * (1.f / 1024.f) - mus * mus + EPSF);

    sa = 0.f; sb = 0.f;
#pragma unroll
    for (int i = 0; i < 4; i++) { sa += h[i]; sb += h[i] * h[i]; }
    r = blockReduce2(sa, sb);
    float muh = r.x * (1.f / 1024.f);
    float rh = rsqrtf(r.y * (1.f / 1024.f) - muh * muh + EPSF);

    float4 g4 = *(const float4*)(gg + tid * 4);
    float4 b4 = *(const float4*)(gb + tid * 4);
    float4 f4 = *(const float4*)(bf + tid * 4);
    float gA[4] = { g4.x, g4.y, g4.z, g4.w };
    float bA[4] = { b4.x, b4.y, b4.z, b4.w };
    float fA[4] = { f4.x, f4.y, f4.z, f4.w };

    float t[4];
    sa = 0.f; sb = 0.f;
#pragma unroll
    for (int i = 0; i < 4; i++) {
        float sf = (s[i] - mus) * rs * gA[i] + bA[i];
        float hf = (h[i] - muh) * rh * gA[i] + bA[i];
        float f = 1.f / (1.f + expf(-(sf + hf + fA[i])));
        float ti = f * sf + (1.f - f) * hf;
        t[i] = ti; sa += ti; sb += ti * ti;
    }
    r = blockReduce2(sa, sb);
    float mut = r.x * (1.f / 1024.f);
    float rt = rsqrtf(r.y * (1.f / 1024.f) - mut * mut + EPSF);
    float4 o;
    o.x = (t[0] - mut) * rt * gA[0] + bA[0];
    o.y = (t[1] - mut) * rt * gA[1] + bA[1];
    o.z = (t[2] - mut) * rt * gA[2] + bA[2];
    o.w = (t[3] - mut) * rt * gA[3] + bA[3];
    *(float4*)(out + base) = o;
    __half2 h0 = __floats2half2_rn(o.x, o.y);
    __half2 h1 = __floats2half2_rn(o.z, o.w);
    uint2 u = { *(uint32_t*)&h0, *(uint32_t*)&h1 };
    *(uint2*)(outh + base) = u;
}

// ---------------- banded attention colsum via fp16 MMA ---------------------------
__global__ void __launch_bounds__(256)
attn_mma(const __half* __restrict__ qh, const __half* __restrict__ kh,
         float* __restrict__ colsum)
{
    __shared__ __half Qs[32][72];
    __shared__ __half Ks[128][72];
    __shared__ float csm[128];
    __shared__ float pmax[32][4];
    __shared__ float psum[32][4];

    const int tid = threadIdx.x, lane = tid & 31, wid = tid >> 5;
    const int wm = wid & 1, wn = wid >> 1;      // warp grid 2(m) x 4(n)
    const int ml = lane >> 2, cl = lane & 3;
    const int nb = blockIdx.z, hh = blockIdx.y;
    const int qb0 = blockIdx.x * 32;
    const int kb0 = qb0 - 96;

    if (tid < 128) csm[tid] = 0.f;

    {
        int row = tid >> 3, seg = tid & 7;
        const __half* src = qh + (((size_t)nb * Sn + qb0 + row) * Hn + hh) * 64 + seg * 8;
        cpa16(&Qs[row][seg * 8], src);
    }
#pragma unroll
    for (int i = 0; i < 4; i++){
        int idx = tid + i * 256;
        int row = idx >> 3, seg = idx & 7;
        int kg = kb0 + row;
        if (kg >= 0){
            const __half* src = kh + (((size_t)nb * Sn + kg) * Hn + hh) * 64 + seg * 8;
            cpa16(&Ks[row][seg * 8], src);
        } else {
            uint4 z = {0u, 0u, 0u, 0u};
            *(uint4*)&Ks[row][seg * 8] = z;
        }
    }
    CP_COMMIT();
    CP_WAIT(0);
    __syncthreads();

    const uint32_t* Qu = (const uint32_t*)Qs;    // 36 u32 per row
    const uint32_t* Ku = (const uint32_t*)Ks;

    float c[4][4];
#pragma unroll
    for (int nt = 0; nt < 4; nt++)
#pragma unroll
        for (int j = 0; j < 4; j++) c[nt][j] = 0.f;

    const int m = wm * 16 + ml;
#pragma unroll
    for (int kk = 0; kk < 4; kk++){
        uint32_t af[4], bf[4][2];
        af[0] = Qu[m * 36 + kk * 8 + cl];
        af[1] = Qu[(m + 8) * 36 + kk * 8 + cl];
        af[2] = Qu[m * 36 + kk * 8 + cl + 4];
        af[3] = Qu[(m + 8) * 36 + kk * 8 + cl + 4];
#pragma unroll
        for (int nt = 0; nt < 4; nt++){
            const int n = wn * 32 + nt * 8 + ml;
            bf[nt][0] = Ku[n * 36 + kk * 8 + cl];
            bf[nt][1] = Ku[n * 36 + kk * 8 + cl + 4];
        }
#pragma unroll
        for (int nt = 0; nt < 4; nt++)
            mma_16816(c[nt], af, bf[nt]);
    }

    const int r_lo = wm * 16 + ml, r_hi = r_lo + 8;
    float lg[4][4];
    float mx_lo = -3.4e38f, mx_hi = -3.4e38f;
#pragma unroll
    for (int nt = 0; nt < 4; nt++){
#pragma unroll
        for (int j = 0; j < 4; j++){
            int col = wn * 32 + nt * 8 + 2 * cl + (j & 1);
            int row = (j < 2) ? r_lo : r_hi;
            int qg = qb0 + row, kg = kb0 + col;
            bool valid = (qg >= 1) && (kg >= 0) && (col >= row) && (col < row + 96);
            float v = valid ? c[nt][j] * 0.03125f - (float)(96 + row - col) : -3.4e38f;
            lg[nt][j] = v;
            if (j < 2) mx_lo = fmaxf(mx_lo, v); else mx_hi = fmaxf(mx_hi, v);
        }
    }
    mx_lo = fmaxf(mx_lo, __shfl_xor_sync(0xffffffffu, mx_lo, 1));
    mx_lo = fmaxf(mx_lo, __shfl_xor_sync(0xffffffffu, mx_lo, 2));
    mx_hi = fmaxf(mx_hi, __shfl_xor_sync(0xffffffffu, mx_hi, 1));
    mx_hi = fmaxf(mx_hi, __shfl_xor_sync(0xffffffffu, mx_hi, 2));
    if (cl == 0){ pmax[r_lo][wn] = mx_lo; pmax[r_hi][wn] = mx_hi; }
    __syncthreads();
    float rm_lo = fmaxf(fmaxf(pmax[r_lo][0], pmax[r_lo][1]),
                        fmaxf(pmax[r_lo][2], pmax[r_lo][3]));
    float rm_hi = fmaxf(fmaxf(pmax[r_hi][0], pmax[r_hi][1]),
                        fmaxf(pmax[r_hi][2], pmax[r_hi][3]));

    float p[4][4];
    float s_lo = 0.f, s_hi = 0.f;
#pragma unroll
    for (int nt = 0; nt < 4; nt++){
#pragma unroll
        for (int j = 0; j < 4; j++){
            float v = lg[nt][j];
            float e = (v > -1e30f) ? expf(v - ((j < 2) ? rm_lo : rm_hi)) : 0.f;
            p[nt][j] = e;
            if (j < 2) s_lo += e; else s_hi += e;
        }
    }
    s_lo += __shfl_xor_sync(0xffffffffu, s_lo, 1);
    s_lo += __shfl_xor_sync(0xffffffffu, s_lo, 2);
    s_hi += __shfl_xor_sync(0xffffffffu, s_hi, 1);
    s_hi += __shfl_xor_sync(0xffffffffu, s_hi, 2);
    if (cl == 0){ psum[r_lo][wn] = s_lo; psum[r_hi][wn] = s_hi; }
    __syncthreads();
    float Z_lo = psum[r_lo][0] + psum[r_lo][1] + psum[r_lo][2] + psum[r_lo][3];
    float Z_hi = psum[r_hi][0] + psum[r_hi][1] + psum[r_hi][2] + psum[r_hi][3];
    float iz_lo = (Z_lo > 0.f) ? 1.f / Z_lo : 0.f;
    float iz_hi = (Z_hi > 0.f) ? 1.f / Z_hi : 0.f;

#pragma unroll
    for (int nt = 0; nt < 4; nt++){
#pragma unroll
        for (int j = 0; j < 4; j++){
            float val = p[nt][j] * ((j < 2) ? iz_lo : iz_hi);
            if (val != 0.f){
                int col = wn * 32 + nt * 8 + 2 * cl + (j & 1);
                atomicAdd(&csm[col], val);
            }
        }
    }
    __syncthreads();

    float* dst = colsum + (size_t)(nb * Hn + hh) * Sn;
    for (int i = tid; i < 128; i += 256){
        int kg = kb0 + i;
        if (kg >= 0 && csm[i] != 0.f) atomicAdd(&dst[kg], csm[i]);
    }
}

// ---------------- elementwise: attn_out (fp16) = v_ln(fp16) * colsum --------------
__global__ void scale_v_kernel(const __half* __restrict__ vln, const float* __restrict__ colsum,
                               __half* __restrict__ out)
{
    int idx = blockIdx.x * blockDim.x + threadIdx.x;
    int token = idx >> 10;
    int n = token >> 10;
    int sidx = token & 1023;
    int h = (idx >> 6) & 15;
    out[idx] = __float2half(__half2float(vln[idx]) *
                            colsum[(((size_t)n * Hn + h) << 10) + sidx]);
}

// ---------------- host orchestration ----------------
extern "C" void kernel_launch(void* const* d_in, const int* in_sizes, int n_in,
                              void* d_out, int out_size)
{
    const float* x     = (const float*)d_in[0];
    const float* Wq    = (const float*)d_in[2];
    const float* Wk    = (const float*)d_in[3];
    const float* Wv    = (const float*)d_in[4];
    const float* ln1g  = (const float*)d_in[5];
    const float* ln1b  = (const float*)d_in[6];
    const float* Wo    = (const float*)d_in[7];
    const float* bo    = (const float*)d_in[8];
    const float* ln2g  = (const float*)d_in[9];
    const float* ln2b  = (const float*)d_in[10];
    const float* Ws    = (const float*)d_in[11];
    const float* Wh    = (const float*)d_in[12];
    const float* bf    = (const float*)d_in[13];
    const float* lnfgg = (const float*)d_in[14];
    const float* lnfgb = (const float*)d_in[15];
    const float* Wp1   = (const float*)d_in[16];
    const float* bp1   = (const float*)d_in[17];
    const float* Wp2   = (const float*)d_in[18];
    const float* bp2   = (const float*)d_in[19];
    const float* lnffg = (const float*)d_in[20];
    const float* lnffb = (const float*)d_in[21];
    float* out = (float*)d_out;

    float *gq, *t1, *t2, *t3, *cs;
    __half *xh, *wqh, *wkh, *wvh, *wsh, *woh, *whh, *wp1h, *wp2h;
    __half *qh, *t1h, *gh, *ffh, *qh16, *kh16;
    cudaGetSymbolAddress((void**)&gq, g_q);
    cudaGetSymbolAddress((void**)&t1, g_t1);
    cudaGetSymbolAddress((void**)&t2, g_t2);
    cudaGetSymbolAddress((void**)&t3, g_t3);
    cudaGetSymbolAddress((void**)&cs, g_cs);
    cudaGetSymbolAddress((void**)&xh,  g_xh);
    cudaGetSymbolAddress((void**)&wqh, g_wqh);
    cudaGetSymbolAddress((void**)&wkh, g_wkh);
    cudaGetSymbolAddress((void**)&wvh, g_wvh);
    cudaGetSymbolAddress((void**)&wsh, g_wsh);
    cudaGetSymbolAddress((void**)&woh, g_woh);
    cudaGetSymbolAddress((void**)&whh, g_whh);
    cudaGetSymbolAddress((void**)&wp1h, g_wp1h);
    cudaGetSymbolAddress((void**)&wp2h, g_wp2h);
    cudaGetSymbolAddress((void**)&qh,  g_qh);
    cudaGetSymbolAddress((void**)&t1h, g_t1h);
    cudaGetSymbolAddress((void**)&gh,  g_gh);
    cudaGetSymbolAddress((void**)&ffh, g_ffh);
    cudaGetSymbolAddress((void**)&qh16, g_qh16);
    cudaGetSymbolAddress((void**)&kh16, g_kh16);
    __half* vh16 = xh;   // xh dead after QKV/Ws GEMM; reuse for v_ln fp16

    cudaFuncSetAttribute(gemm_h, cudaFuncAttributeMaxDynamicSharedMemorySize, GEMM_SMEM);

    // convert x + all weights to fp16; slice 9 initializes colsum to 1/1024
    {
        CV10 cb;
        cb.s[0]=x;   cb.d[0]=xh;   cb.n[0]=TOK*Dn;
        cb.s[1]=Wq;  cb.d[1]=wqh;  cb.n[1]=Dn*Dn;
        cb.s[2]=Wk;  cb.d[2]=wkh;  cb.n[2]=Dn*Dn;
        cb.s[3]=Wv;  cb.d[3]=wvh;  cb.n[3]=Dn*Dn;
        cb.s[4]=Ws;  cb.d[4]=wsh;  cb.n[4]=Dn*Dn;
        cb.s[5]=Wo;  cb.d[5]=woh;  cb.n[5]=Dn*Dn;
        cb.s[6]=Wh;  cb.d[6]=whh;  cb.n[6]=Dn*Dn;
        cb.s[7]=Wp1; cb.d[7]=wp1h; cb.n[7]=DFFn*Dn;
        cb.s[8]=Wp2; cb.d[8]=wp2h; cb.n[8]=Dn*DFFn;
        cb.cs = cs; cb.ncs = Bn*Hn*Sn;
        conv_f2h<<<dim3(DFFn*Dn/4/256, 10), 256>>>(cb);
    }

    // QKV + Ws projections in one batched launch (A = xh)
    // q,k,v -> fp16-only scratch (qh, t1h, gh); Ws -> t2 fp32 (gate input)
    {
        GB gb;
        gb.W[0] = wqh; gb.W[1] = wkh; gb.W[2] = wvh; gb.W[3] = wsh;
        gb.C[0] = nullptr; gb.C[1] = nullptr; gb.C[2] = nullptr; gb.C[3] = t2;
        gb.Ch[0] = qh; gb.Ch[1] = t1h; gb.Ch[2] = gh; gb.Ch[3] = nullptr;
        gb.bias[0] = gb.bias[1] = gb.bias[2] = gb.bias[3] = nullptr;
        gemm_h<<<dim3(8, 32, 4), 256, GEMM_SMEM>>>(xh, gb, Dn, Dn, Dn, Dn, 0);
    }

    // per-head LN: q,k,v fp16 -> fp16 LN'd buffers
    {
        LNBH b3;
        b3.in[0] = qh;   b3.in[1] = t1h;  b3.in[2] = gh;
        b3.out[0] = qh16; b3.out[1] = kh16; b3.out[2] = vh16;
        ln_head_kernel<<<dim3(TOK * Hn / 8, 3), 256>>>(b3, ln1g, ln1b);
    }

    // banded attention colsum (MMA path); colsum pre-initialized by conv slice 9
    attn_mma<<<dim3(Sn / 32, Hn, Bn), 256>>>(qh16, kh16, cs);

    // attn_out (fp16) = v_ln * colsum  (qh reused after ln_head consumed it)
    scale_v_kernel<<<(TOK * Dn) / 256, 256>>>(vh16, cs, qh);

    // output projection + LN -> h (t1 fp32 + t1h fp16)
    {
        GB gb; gb.W[0] = woh; gb.C[0] = t1; gb.Ch[0] = nullptr; gb.bias[0] = bo;
        gemm_h<<<dim3(8, 32, 1), 256, GEMM_SMEM>>>(qh, gb, Dn, Dn, Dn, Dn, 0);
    }
    ln1024_kernel<<<TOK, 256>>>(t1, nullptr, ln2g, ln2b, t1, t1h);

    // fusion gate (t2 = x@Ws^T computed above)
    {
        GB gb; gb.W[0] = whh; gb.C[0] = t3; gb.Ch[0] = nullptr; gb.bias[0] = nullptr;
        gemm_h<<<dim3(8, 32, 1), 256, GEMM_SMEM>>>(t1h, gb, Dn, Dn, Dn, Dn, 0);
    }
    gate_kernel<<<TOK, 256>>>(t2, t3, bf, lnfgg, lnfgb, gq, gh);  // g fp32 -> gq, fp16 -> gh

    // FFN (FFN1 writes fp16 only; FFN2 fp32)
    {
        GB gb; gb.W[0] = wp1h; gb.C[0] = nullptr; gb.Ch[0] = ffh; gb.bias[0] = bp1;
        gemm_h<<<dim3(32, 32, 1), 256, GEMM_SMEM>>>(gh, gb, Dn, Dn, Dn, DFFn, 1);
    }
    {
        GB gb; gb.W[0] = wp2h; gb.C[0] = t3; gb.Ch[0] = nullptr; gb.bias[0] = bp2;
        gemm_h<<<dim3(8, 32, 1), 256, GEMM_SMEM>>>(ffh, gb, DFFn, DFFn, DFFn, Dn, 0);
    }

    // final residual + LN
    ln1024_kernel<<<TOK, 256>>>(t3, gq, lnffg, lnffb, out, nullptr);
}

// round 14
// speedup vs baseline: 1.0669x; 1.0370x over previous
#include <cuda_runtime.h>
#include <cuda_fp16.h>
#include <math.h>
#include <stdint.h>

// Problem constants
#define Bn   4
#define Sn   1024
#define Dn   1024
#define Hn   16
#define DHn  64
#define DFFn 4096
#define TOK  (Bn*Sn)          // 4096
#define EPSF 1e-5f
#define NEGF (-1e20f)

// ---------------- static device workspaces ----------------
__device__ float g_q [TOK*Dn];     // gate g fp32 target
__device__ float g_t1[TOK*Dn];
__device__ float g_t2[TOK*Dn];
__device__ float g_t3[TOK*Dn];
__device__ float g_cs[Bn*Hn*Sn];

__device__ __half g_xh [TOK*Dn];     // x fp16
__device__ __half g_wqh[Dn*Dn];
__device__ __half g_wkh[Dn*Dn];
__device__ __half g_wvh[Dn*Dn];
__device__ __half g_wsh[Dn*Dn];
__device__ __half g_woh[Dn*Dn];
__device__ __half g_whh[Dn*Dn];
__device__ __half g_wp1h[DFFn*Dn];
__device__ __half g_wp2h[Dn*DFFn];
__device__ __half g_qh [TOK*Dn];    // QKV q out (raw); later attn_out
__device__ __half g_t1h[TOK*Dn];    // QKV k out (raw); later ln1024 h out
__device__ __half g_gh [TOK*Dn];    // QKV v out (raw); later gate g out
__device__ __half g_ffh[TOK*DFFn];

// ---------------- helpers ----------------
__device__ __forceinline__ void mma_16816(float* c, const uint32_t* a, const uint32_t* b){
    asm volatile(
        "mma.sync.aligned.m16n8k16.row.col.f32.f16.f16.f32 "
        "{%0,%1,%2,%3}, {%4,%5,%6,%7}, {%8,%9}, {%0,%1,%2,%3};"
        : "+f"(c[0]), "+f"(c[1]), "+f"(c[2]), "+f"(c[3])
        : "r"(a[0]), "r"(a[1]), "r"(a[2]), "r"(a[3]), "r"(b[0]), "r"(b[1]));
}
__device__ __forceinline__ void cpa16(void* dst, const void* src){
    uint32_t d = (uint32_t)__cvta_generic_to_shared(dst);
    asm volatile("cp.async.ca.shared.global [%0], [%1], 16;" :: "r"(d), "l"(src));
}
#define CP_COMMIT() asm volatile("cp.async.commit_group;" ::: "memory")
#define CP_WAIT(N)  asm volatile("cp.async.wait_group %0;" :: "n"(N) : "memory")

// ---------------- batched fp32 -> fp16 conversion + colsum init ----------------
struct CV10 { const float* s[9]; __half* d[9]; int n[9]; float* cs; int ncs; };
__global__ void conv_f2h(CV10 cb)
{
    const int m = blockIdx.y;
    int i = (blockIdx.x * 256 + threadIdx.x) * 4;
    if (m == 9){
        if (i < cb.ncs){
            float4 u = { 1.f/1024.f, 1.f/1024.f, 1.f/1024.f, 1.f/1024.f };
            *(float4*)(cb.cs + i) = u;
        }
        return;
    }
    const float* s = cb.s[m];
    __half* d = cb.d[m];
    if (i < cb.n[m]){
        float4 v = *(const float4*)(s + i);
        __half2 h0 = __floats2half2_rn(v.x, v.y);
        __half2 h1 = __floats2half2_rn(v.z, v.w);
        uint2 u = { *(uint32_t*)&h0, *(uint32_t*)&h1 };
        *(uint2*)(d + i) = u;
    }
}

// batch descriptor (kernel param by value; blockIdx.z selects)
struct GB {
    const __half* W[4];
    float*        C[4];
    __half*       Ch[4];
    const float*  bias[4];
};

// ---------------- fp16 mma.sync GEMM (m16n8k16, BK=32, cp.async 3-stage) ---------
__global__ void __launch_bounds__(256, 2)
gemm_h(const __half* __restrict__ A, GB gb,
       int K, int lda, int ldb, int ldc, int flags)
{
    extern __shared__ __half sm[];
    __half (*As)[128][40] = (__half(*)[128][40])sm;
    __half (*Bs)[128][40] = (__half(*)[128][40])(sm + 3 * 128 * 40);

    const __half* W    = gb.W[blockIdx.z];
    float*        C    = gb.C[blockIdx.z];
    __half*       Ch   = gb.Ch[blockIdx.z];
    const float*  bias = gb.bias[blockIdx.z];

    const int tid = threadIdx.x, lane = tid & 31, wid = tid >> 5;
    const int wm = wid & 1, wn = wid >> 1;          // warp grid 2 x 4
    const int ml = lane >> 2, cl = lane & 3;

    const int r0 = tid >> 1;                // tile row 0..127
    const int kh = (tid & 1) * 16;          // k half-chunk 0 or 16 (halves)
    const __half* Ap = A + ((size_t)blockIdx.y * 128 + r0) * lda + kh;
    const __half* Wp = W + ((size_t)blockIdx.x * 128 + r0) * ldb + kh;

    float acc[4][4][4];
#pragma unroll
    for (int i = 0; i < 4; i++)
#pragma unroll
        for (int j = 0; j < 4; j++)
#pragma unroll
            for (int r = 0; r < 4; r++) acc[i][j][r] = 0.f;

    const int T = K >> 5;

#define ISSUE(t, s) do { \
    const __half* a_ = Ap + (size_t)(t) * 32; \
    const __half* w_ = Wp + (size_t)(t) * 32; \
    cpa16(&As[s][r0][kh],     a_);  cpa16(&As[s][r0][kh + 8], a_ + 8); \
    cpa16(&Bs[s][r0][kh],     w_);  cpa16(&Bs[s][r0][kh + 8], w_ + 8); \
    CP_COMMIT(); \
} while(0)

    ISSUE(0, 0);
    ISSUE(1, 1);

#pragma unroll 1
    for (int t = 0; t < T; t++){
        const int s = t % 3;
        if (t + 1 < T) { CP_WAIT(1); } else { CP_WAIT(0); }
        __syncthreads();

        const uint32_t* Au = (const uint32_t*)As[s];   // 20 u32 per row
        const uint32_t* Bu = (const uint32_t*)Bs[s];
#pragma unroll
        for (int kk = 0; kk < 2; kk++){
            uint32_t af[4][4], bf[4][2];
#pragma unroll
            for (int mt = 0; mt < 4; mt++){
                const int m = wm * 64 + mt * 16 + ml;
                af[mt][0] = Au[m * 20 + kk * 8 + cl];
                af[mt][1] = Au[(m + 8) * 20 + kk * 8 + cl];
                af[mt][2] = Au[m * 20 + kk * 8 + cl + 4];
                af[mt][3] = Au[(m + 8) * 20 + kk * 8 + cl + 4];
            }
#pragma unroll
            for (int nt = 0; nt < 4; nt++){
                const int n = wn * 32 + nt * 8 + ml;
                bf[nt][0] = Bu[n * 20 + kk * 8 + cl];
                bf[nt][1] = Bu[n * 20 + kk * 8 + cl + 4];
            }
#pragma unroll
            for (int mt = 0; mt < 4; mt++)
#pragma unroll
                for (int nt = 0; nt < 4; nt++)
                    mma_16816(acc[mt][nt], af[mt], bf[nt]);
        }

        if (t + 2 < T) ISSUE(t + 2, (t + 2) % 3);
    }
#undef ISSUE

    // epilogue
    const int rbase = blockIdx.y * 128 + wm * 64 + ml;
    const int cbase = blockIdx.x * 128 + wn * 32 + 2 * cl;
#pragma unroll
    for (int mt = 0; mt < 4; mt++){
#pragma unroll
        for (int nt = 0; nt < 4; nt++){
            const int row = rbase + mt * 16;
            const int col = cbase + nt * 8;
            float bx0 = 0.f, bx1 = 0.f;
            if (bias){ bx0 = bias[col]; bx1 = bias[col + 1]; }
            float v00 = acc[mt][nt][0] + bx0, v01 = acc[mt][nt][1] + bx1;
            float v10 = acc[mt][nt][2] + bx0, v11 = acc[mt][nt][3] + bx1;
            if (flags & 1){
                v00 = fmaxf(v00, 0.f); v01 = fmaxf(v01, 0.f);
                v10 = fmaxf(v10, 0.f); v11 = fmaxf(v11, 0.f);
            }
            if (C){
                float2 u0 = { v00, v01 }, u1 = { v10, v11 };
                *(float2*)&C[(size_t)row * ldc + col] = u0;
                *(float2*)&C[(size_t)(row + 8) * ldc + col] = u1;
            }
            if (Ch){
                __half2 h0 = __floats2half2_rn(v00, v01);
                __half2 h1 = __floats2half2_rn(v10, v11);
                *(__half2*)&Ch[(size_t)row * ldc + col] = h0;
                *(__half2*)&Ch[(size_t)(row + 8) * ldc + col] = h1;
            }
        }
    }
}
#define GEMM_SMEM (3 * 128 * 40 * 2 * 2)   // 61440 B dynamic

// ---------------- block reduction helper ----------------
__device__ __forceinline__ float2 blockReduce2(float a, float b)
{
    __shared__ float sa[8], sb[8];
    int lane = threadIdx.x & 31, w = threadIdx.x >> 5;
#pragma unroll
    for (int off = 16; off; off >>= 1) {
        a += __shfl_xor_sync(0xffffffffu, a, off);
        b += __shfl_xor_sync(0xffffffffu, b, off);
    }
    __syncthreads();
    if (lane == 0) { sa[w] = a; sb[w] = b; }
    __syncthreads();
    float ra = 0.f, rb = 0.f;
#pragma unroll
    for (int i = 0; i < 8; i++) { ra += sa[i]; rb += sb[i]; }
    return make_float2(ra, rb);
}

// ---------------- layernorm over D=1024 (+opt residual, +opt fp32/fp16 out) -------
__global__ void ln1024_kernel(const float* __restrict__ in, const float* __restrict__ res,
                              const float* __restrict__ g, const float* __restrict__ b,
                              float* __restrict__ out, __half* __restrict__ outh)
{
    int row = blockIdx.x, tid = threadIdx.x;
    size_t base = (size_t)row * 1024 + tid * 4;
    float4 v = *(const float4*)(in + base);
    float x[4] = { v.x, v.y, v.z, v.w };
    if (res) {
        float4 rv = *(const float4*)(res + base);
        x[0] += rv.x; x[1] += rv.y; x[2] += rv.z; x[3] += rv.w;
    }
    float sa = 0.f, sb = 0.f;
#pragma unroll
    for (int i = 0; i < 4; i++) { sa += x[i]; sb += x[i] * x[i]; }
    float2 r = blockReduce2(sa, sb);
    float mu = r.x * (1.f / 1024.f);
    float var = r.y * (1.f / 1024.f) - mu * mu;
    float rs = rsqrtf(var + EPSF);
    float4 g4 = *(const float4*)(g + tid * 4);
    float4 b4 = *(const float4*)(b + tid * 4);
    float4 o;
    o.x = (x[0] - mu) * rs * g4.x + b4.x;
    o.y = (x[1] - mu) * rs * g4.y + b4.y;
    o.z = (x[2] - mu) * rs * g4.z + b4.z;
    o.w = (x[3] - mu) * rs * g4.w + b4.w;
    if (out) *(float4*)(out + base) = o;
    if (outh){
        __half2 h0 = __floats2half2_rn(o.x, o.y);
        __half2 h1 = __floats2half2_rn(o.z, o.w);
        uint2 u = { *(uint32_t*)&h0, *(uint32_t*)&h1 };
        *(uint2*)(outh + base) = u;
    }
}

// ---------------- fused gate (fp32 g out + fp16 g out) ----------------------------
__global__ void gate_kernel(const float* __restrict__ sp, const float* __restrict__ hp,
                            const float* __restrict__ bf,
                            const float* __restrict__ gg, const float* __restrict__ gb,
                            float* __restrict__ out, __half* __restrict__ outh)
{
    int row = blockIdx.x, tid = threadIdx.x;
    size_t base = (size_t)row * 1024 + tid * 4;
    float4 sv = *(const float4*)(sp + base);
    float4 hv = *(const float4*)(hp + base);
    float s[4] = { sv.x, sv.y, sv.z, sv.w };
    float h[4] = { hv.x, hv.y, hv.z, hv.w };

    float sa = 0.f, sb = 0.f;
#pragma unroll
    for (int i = 0; i < 4; i++) { sa += s[i]; sb += s[i] * s[i]; }
    float2 r = blockReduce2(sa, sb);
    float mus = r.x * (1.f / 1024.f);
    float rs = rsqrtf(r.y * (1.f / 1024.f) - mus * mus + EPSF);

    sa = 0.f; sb = 0.f;
#pragma unroll
    for (int i = 0; i < 4; i++) { sa += h[i]; sb += h[i] * h[i]; }
    r = blockReduce2(sa, sb);
    float muh = r.x * (1.f / 1024.f);
    float rh = rsqrtf(r.y * (1.f / 1024.f) - muh * muh + EPSF);

    float4 g4 = *(const float4*)(gg + tid * 4);
    float4 b4 = *(const float4*)(gb + tid * 4);
    float4 f4 = *(const float4*)(bf + tid * 4);
    float gA[4] = { g4.x, g4.y, g4.z, g4.w };
    float bA[4] = { b4.x, b4.y, b4.z, b4.w };
    float fA[4] = { f4.x, f4.y, f4.z, f4.w };

    float t[4];
    sa = 0.f; sb = 0.f;
#pragma unroll
    for (int i = 0; i < 4; i++) {
        float sf = (s[i] - mus) * rs * gA[i] + bA[i];
        float hf = (h[i] - muh) * rh * gA[i] + bA[i];
        float f = 1.f / (1.f + expf(-(sf + hf + fA[i])));
        float ti = f * sf + (1.f - f) * hf;
        t[i] = ti; sa += ti; sb += ti * ti;
    }
    r = blockReduce2(sa, sb);
    float mut = r.x * (1.f / 1024.f);
    float rt = rsqrtf(r.y * (1.f / 1024.f) - mut * mut + EPSF);
    float4 o;
    o.x = (t[0] - mut) * rt * gA[0] + bA[0];
    o.y = (t[1] - mut) * rt * gA[1] + bA[1];
    o.z = (t[2] - mut) * rt * gA[2] + bA[2];
    o.w = (t[3] - mut) * rt * gA[3] + bA[3];
    *(float4*)(out + base) = o;
    __half2 h0 = __floats2half2_rn(o.x, o.y);
    __half2 h1 = __floats2half2_rn(o.z, o.w);
    uint2 u = { *(uint32_t*)&h0, *(uint32_t*)&h1 };
    *(uint2*)(outh + base) = u;
}

// ---------------- banded attention colsum via fp16 MMA + fused per-head LN --------
// Loads RAW q,k tiles; LNs each 64-half row in smem (row == one (token,head) LN
// unit), then proceeds as before. K rows with kg<0 are zero-filled; their LN
// output is garbage but masked out of the logits.
__global__ void __launch_bounds__(256)
attn_mma(const __half* __restrict__ qh, const __half* __restrict__ kh,
         const float* __restrict__ lng, const float* __restrict__ lnb,
         float* __restrict__ colsum)
{
    __shared__ __half Qs[32][72];
    __shared__ __half Ks[128][72];
    __shared__ float csm[128];
    __shared__ float pmax[32][4];
    __shared__ float psum[32][4];

    const int tid = threadIdx.x, lane = tid & 31, wid = tid >> 5;
    const int wm = wid & 1, wn = wid >> 1;      // warp grid 2(m) x 4(n)
    const int ml = lane >> 2, cl = lane & 3;
    const int nb = blockIdx.z, hh = blockIdx.y;
    const int qb0 = blockIdx.x * 32;
    const int kb0 = qb0 - 96;

    if (tid < 128) csm[tid] = 0.f;

    {
        int row = tid >> 3, seg = tid & 7;
        const __half* src = qh + (((size_t)nb * Sn + qb0 + row) * Hn + hh) * 64 + seg * 8;
        cpa16(&Qs[row][seg * 8], src);
    }
#pragma unroll
    for (int i = 0; i < 4; i++){
        int idx = tid + i * 256;
        int row = idx >> 3, seg = idx & 7;
        int kg = kb0 + row;
        if (kg >= 0){
            const __half* src = kh + (((size_t)nb * Sn + kg) * Hn + hh) * 64 + seg * 8;
            cpa16(&Ks[row][seg * 8], src);
        } else {
            uint4 z = {0u, 0u, 0u, 0u};
            *(uint4*)&Ks[row][seg * 8] = z;
        }
    }
    CP_COMMIT();
    CP_WAIT(0);
    __syncthreads();

    // fused per-head LN of all 160 rows (warp-per-row, 20 rows/warp)
    {
        const float gv0 = lng[lane], gv1 = lng[lane + 32];
        const float bv0 = lnb[lane], bv1 = lnb[lane + 32];
        for (int r = wid; r < 160; r += 8){
            __half* rowp = (r < 32) ? &Qs[r][0] : &Ks[r - 32][0];
            float v0 = __half2float(rowp[lane]);
            float v1 = __half2float(rowp[lane + 32]);
            float s = v0 + v1;
#pragma unroll
            for (int o = 16; o; o >>= 1) s += __shfl_xor_sync(0xffffffffu, s, o);
            float mu = s * (1.f / 64.f);
            float d0 = v0 - mu, d1 = v1 - mu;
            float qq = d0 * d0 + d1 * d1;
#pragma unroll
            for (int o = 16; o; o >>= 1) qq += __shfl_xor_sync(0xffffffffu, qq, o);
            float rr = rsqrtf(qq * (1.f / 64.f) + EPSF);
            rowp[lane]      = __float2half(d0 * rr * gv0 + bv0);
            rowp[lane + 32] = __float2half(d1 * rr * gv1 + bv1);
        }
    }
    __syncthreads();

    const uint32_t* Qu = (const uint32_t*)Qs;    // 36 u32 per row
    const uint32_t* Ku = (const uint32_t*)Ks;

    float c[4][4];
#pragma unroll
    for (int nt = 0; nt < 4; nt++)
#pragma unroll
        for (int j = 0; j < 4; j++) c[nt][j] = 0.f;

    const int m = wm * 16 + ml;
#pragma unroll
    for (int kk = 0; kk < 4; kk++){
        uint32_t af[4], bf[4][2];
        af[0] = Qu[m * 36 + kk * 8 + cl];
        af[1] = Qu[(m + 8) * 36 + kk * 8 + cl];
        af[2] = Qu[m * 36 + kk * 8 + cl + 4];
        af[3] = Qu[(m + 8) * 36 + kk * 8 + cl + 4];
#pragma unroll
        for (int nt = 0; nt < 4; nt++){
            const int n = wn * 32 + nt * 8 + ml;
            bf[nt][0] = Ku[n * 36 + kk * 8 + cl];
            bf[nt][1] = Ku[n * 36 + kk * 8 + cl + 4];
        }
#pragma unroll
        for (int nt = 0; nt < 4; nt++)
            mma_16816(c[nt], af, bf[nt]);
    }

    const int r_lo = wm * 16 + ml, r_hi = r_lo + 8;
    float lg[4][4];
    float mx_lo = -3.4e38f, mx_hi = -3.4e38f;
#pragma unroll
    for (int nt = 0; nt < 4; nt++){
#pragma unroll
        for (int j = 0; j < 4; j++){
            int col = wn * 32 + nt * 8 + 2 * cl + (j & 1);
            int row = (j < 2) ? r_lo : r_hi;
            int qg = qb0 + row, kg = kb0 + col;
            bool valid = (qg >= 1) && (kg >= 0) && (col >= row) && (col < row + 96);
            float v = valid ? c[nt][j] * 0.03125f - (float)(96 + row - col) : -3.4e38f;
            lg[nt][j] = v;
            if (j < 2) mx_lo = fmaxf(mx_lo, v); else mx_hi = fmaxf(mx_hi, v);
        }
    }
    mx_lo = fmaxf(mx_lo, __shfl_xor_sync(0xffffffffu, mx_lo, 1));
    mx_lo = fmaxf(mx_lo, __shfl_xor_sync(0xffffffffu, mx_lo, 2));
    mx_hi = fmaxf(mx_hi, __shfl_xor_sync(0xffffffffu, mx_hi, 1));
    mx_hi = fmaxf(mx_hi, __shfl_xor_sync(0xffffffffu, mx_hi, 2));
    if (cl == 0){ pmax[r_lo][wn] = mx_lo; pmax[r_hi][wn] = mx_hi; }
    __syncthreads();
    float rm_lo = fmaxf(fmaxf(pmax[r_lo][0], pmax[r_lo][1]),
                        fmaxf(pmax[r_lo][2], pmax[r_lo][3]));
    float rm_hi = fmaxf(fmaxf(pmax[r_hi][0], pmax[r_hi][1]),
                        fmaxf(pmax[r_hi][2], pmax[r_hi][3]));

    float p[4][4];
    float s_lo = 0.f, s_hi = 0.f;
#pragma unroll
    for (int nt = 0; nt < 4; nt++){
#pragma unroll
        for (int j = 0; j < 4; j++){
            float v = lg[nt][j];
            float e = (v > -1e30f) ? expf(v - ((j < 2) ? rm_lo : rm_hi)) : 0.f;
            p[nt][j] = e;
            if (j < 2) s_lo += e; else s_hi += e;
        }
    }
    s_lo += __shfl_xor_sync(0xffffffffu, s_lo, 1);
    s_lo += __shfl_xor_sync(0xffffffffu, s_lo, 2);
    s_hi += __shfl_xor_sync(0xffffffffu, s_hi, 1);
    s_hi += __shfl_xor_sync(0xffffffffu, s_hi, 2);
    if (cl == 0){ psum[r_lo][wn] = s_lo; psum[r_hi][wn] = s_hi; }
    __syncthreads();
    float Z_lo = psum[r_lo][0] + psum[r_lo][1] + psum[r_lo][2] + psum[r_lo][3];
    float Z_hi = psum[r_hi][0] + psum[r_hi][1] + psum[r_hi][2] + psum[r_hi][3];
    float iz_lo = (Z_lo > 0.f) ? 1.f / Z_lo : 0.f;
    float iz_hi = (Z_hi > 0.f) ? 1.f / Z_hi : 0.f;

#pragma unroll
    for (int nt = 0; nt < 4; nt++){
#pragma unroll
        for (int j = 0; j < 4; j++){
            float val = p[nt][j] * ((j < 2) ? iz_lo : iz_hi);
            if (val != 0.f){
                int col = wn * 32 + nt * 8 + 2 * cl + (j & 1);
                atomicAdd(&csm[col], val);
            }
        }
    }
    __syncthreads();

    float* dst = colsum + (size_t)(nb * Hn + hh) * Sn;
    for (int i = tid; i < 128; i += 256){
        int kg = kb0 + i;
        if (kg >= 0 && csm[i] != 0.f) atomicAdd(&dst[kg], csm[i]);
    }
}

// ---------------- fused LN(v) * colsum -> attn_out (fp16), warp-per-head-row ------
__global__ void ln_scale_v(const __half* __restrict__ v,
                           const float* __restrict__ g, const float* __restrict__ b,
                           const float* __restrict__ cs, __half* __restrict__ out)
{
    int row = blockIdx.x * 8 + (threadIdx.x >> 5);   // 0 .. TOK*Hn-1
    int lane = threadIdx.x & 31;
    const __half* p = v + (size_t)row * 64;
    float v0 = __half2float(p[lane]), v1 = __half2float(p[lane + 32]);
    float s = v0 + v1;
#pragma unroll
    for (int o = 16; o; o >>= 1) s += __shfl_xor_sync(0xffffffffu, s, o);
    float mu = s * (1.f / 64.f);
    float d0 = v0 - mu, d1 = v1 - mu;
    float q = d0 * d0 + d1 * d1;
#pragma unroll
    for (int o = 16; o; o >>= 1) q += __shfl_xor_sync(0xffffffffu, q, o);
    float r = rsqrtf(q * (1.f / 64.f) + EPSF);
    int token = row >> 4, h = row & 15;
    float csv = cs[((((size_t)(token >> 10)) * Hn + h) << 10) + (token & 1023)];
    __half* o_ = out + (size_t)row * 64;
    o_[lane]      = __float2half((d0 * r * g[lane]      + b[lane])      * csv);
    o_[lane + 32] = __float2half((d1 * r * g[lane + 32] + b[lane + 32]) * csv);
}

// ---------------- host orchestration ----------------
extern "C" void kernel_launch(void* const* d_in, const int* in_sizes, int n_in,
                              void* d_out, int out_size)
{
    const float* x     = (const float*)d_in[0];
    const float* Wq    = (const float*)d_in[2];
    const float* Wk    = (const float*)d_in[3];
    const float* Wv    = (const float*)d_in[4];
    const float* ln1g  = (const float*)d_in[5];
    const float* ln1b  = (const float*)d_in[6];
    const float* Wo    = (const float*)d_in[7];
    const float* bo    = (const float*)d_in[8];
    const float* ln2g  = (const float*)d_in[9];
    const float* ln2b  = (const float*)d_in[10];
    const float* Ws    = (const float*)d_in[11];
    const float* Wh    = (const float*)d_in[12];
    const float* bf    = (const float*)d_in[13];
    const float* lnfgg = (const float*)d_in[14];
    const float* lnfgb = (const float*)d_in[15];
    const float* Wp1   = (const float*)d_in[16];
    const float* bp1   = (const float*)d_in[17];
    const float* Wp2   = (const float*)d_in[18];
    const float* bp2   = (const float*)d_in[19];
    const float* lnffg = (const float*)d_in[20];
    const float* lnffb = (const float*)d_in[21];
    float* out = (float*)d_out;

    float *gq, *t1, *t2, *t3, *cs;
    __half *xh, *wqh, *wkh, *wvh, *wsh, *woh, *whh, *wp1h, *wp2h;
    __half *qh, *t1h, *gh, *ffh;
    cudaGetSymbolAddress((void**)&gq, g_q);
    cudaGetSymbolAddress((void**)&t1, g_t1);
    cudaGetSymbolAddress((void**)&t2, g_t2);
    cudaGetSymbolAddress((void**)&t3, g_t3);
    cudaGetSymbolAddress((void**)&cs, g_cs);
    cudaGetSymbolAddress((void**)&xh,  g_xh);
    cudaGetSymbolAddress((void**)&wqh, g_wqh);
    cudaGetSymbolAddress((void**)&wkh, g_wkh);
    cudaGetSymbolAddress((void**)&wvh, g_wvh);
    cudaGetSymbolAddress((void**)&wsh, g_wsh);
    cudaGetSymbolAddress((void**)&woh, g_woh);
    cudaGetSymbolAddress((void**)&whh, g_whh);
    cudaGetSymbolAddress((void**)&wp1h, g_wp1h);
    cudaGetSymbolAddress((void**)&wp2h, g_wp2h);
    cudaGetSymbolAddress((void**)&qh,  g_qh);
    cudaGetSymbolAddress((void**)&t1h, g_t1h);
    cudaGetSymbolAddress((void**)&gh,  g_gh);
    cudaGetSymbolAddress((void**)&ffh, g_ffh);
    __half* attn_out = xh;   // xh dead after QKV/Ws GEMM; reuse for attn_out fp16

    cudaFuncSetAttribute(gemm_h, cudaFuncAttributeMaxDynamicSharedMemorySize, GEMM_SMEM);

    // convert x + all weights to fp16; slice 9 initializes colsum to 1/1024
    {
        CV10 cb;
        cb.s[0]=x;   cb.d[0]=xh;   cb.n[0]=TOK*Dn;
        cb.s[1]=Wq;  cb.d[1]=wqh;  cb.n[1]=Dn*Dn;
        cb.s[2]=Wk;  cb.d[2]=wkh;  cb.n[2]=Dn*Dn;
        cb.s[3]=Wv;  cb.d[3]=wvh;  cb.n[3]=Dn*Dn;
        cb.s[4]=Ws;  cb.d[4]=wsh;  cb.n[4]=Dn*Dn;
        cb.s[5]=Wo;  cb.d[5]=woh;  cb.n[5]=Dn*Dn;
        cb.s[6]=Wh;  cb.d[6]=whh;  cb.n[6]=Dn*Dn;
        cb.s[7]=Wp1; cb.d[7]=wp1h; cb.n[7]=DFFn*Dn;
        cb.s[8]=Wp2; cb.d[8]=wp2h; cb.n[8]=Dn*DFFn;
        cb.cs = cs; cb.ncs = Bn*Hn*Sn;
        conv_f2h<<<dim3(DFFn*Dn/4/256, 10), 256>>>(cb);
    }

    // QKV + Ws projections in one batched launch (A = xh)
    // q,k,v -> raw fp16 scratch (qh, t1h, gh); Ws -> t2 fp32 (gate input)
    {
        GB gb;
        gb.W[0] = wqh; gb.W[1] = wkh; gb.W[2] = wvh; gb.W[3] = wsh;
        gb.C[0] = nullptr; gb.C[1] = nullptr; gb.C[2] = nullptr; gb.C[3] = t2;
        gb.Ch[0] = qh; gb.Ch[1] = t1h; gb.Ch[2] = gh; gb.Ch[3] = nullptr;
        gb.bias[0] = gb.bias[1] = gb.bias[2] = gb.bias[3] = nullptr;
        gemm_h<<<dim3(8, 32, 4), 256, GEMM_SMEM>>>(xh, gb, Dn, Dn, Dn, Dn, 0);
    }

    // banded attention colsum (raw q,k; LN fused in-kernel)
    attn_mma<<<dim3(Sn / 32, Hn, Bn), 256>>>(qh, t1h, ln1g, ln1b, cs);

    // attn_out (fp16) = LN(v) * colsum  (fused; writes into xh scratch)
    ln_scale_v<<<TOK * Hn / 8, 256>>>(gh, ln1g, ln1b, cs, attn_out);

    // output projection + LN -> h (t1h fp16 only; fp32 store dropped)
    {
        GB gb; gb.W[0] = woh; gb.C[0] = t1; gb.Ch[0] = nullptr; gb.bias[0] = bo;
        gemm_h<<<dim3(8, 32, 1), 256, GEMM_SMEM>>>(attn_out, gb, Dn, Dn, Dn, Dn, 0);
    }
    ln1024_kernel<<<TOK, 256>>>(t1, nullptr, ln2g, ln2b, nullptr, t1h);

    // fusion gate (t2 = x@Ws^T computed above)
    {
        GB gb; gb.W[0] = whh; gb.C[0] = t3; gb.Ch[0] = nullptr; gb.bias[0] = nullptr;
        gemm_h<<<dim3(8, 32, 1), 256, GEMM_SMEM>>>(t1h, gb, Dn, Dn, Dn, Dn, 0);
    }
    gate_kernel<<<TOK, 256>>>(t2, t3, bf, lnfgg, lnfgb, gq, gh);  // g fp32 -> gq, fp16 -> gh

    // FFN (FFN1 writes fp16 only; FFN2 fp32)
    {
        GB gb; gb.W[0] = wp1h; gb.C[0] = nullptr; gb.Ch[0] = ffh; gb.bias[0] = bp1;
        gemm_h<<<dim3(32, 32, 1), 256, GEMM_SMEM>>>(gh, gb, Dn, Dn, Dn, DFFn, 1);
    }
    {
        GB gb; gb.W[0] = wp2h; gb.C[0] = t3; gb.Ch[0] = nullptr; gb.bias[0] = bp2;
        gemm_h<<<dim3(8, 32, 1), 256, GEMM_SMEM>>>(ffh, gb, DFFn, DFFn, DFFn, Dn, 0);
    }

    // final residual + LN
    ln1024_kernel<<<TOK, 256>>>(t3, gq, lnffg, lnffb, out, nullptr);
}

// round 15
// speedup vs baseline: 1.2360x; 1.1585x over previous
#include <cuda_runtime.h>
#include <cuda_fp16.h>
#include <math.h>
#include <stdint.h>

// Problem constants
#define Bn   4
#define Sn   1024
#define Dn   1024
#define Hn   16
#define DHn  64
#define DFFn 4096
#define TOK  (Bn*Sn)          // 4096
#define EPSF 1e-5f
#define NEGF (-1e20f)

// ---------------- static device workspaces ----------------
__device__ float g_q [TOK*Dn];     // gate g fp32 target
__device__ float g_t1[TOK*Dn];
__device__ float g_t2[TOK*Dn];
__device__ float g_t3[TOK*Dn];
__device__ float g_cs[Bn*Hn*Sn];

__device__ __half g_xh [TOK*Dn];     // x fp16
__device__ __half g_wqh[Dn*Dn];
__device__ __half g_wkh[Dn*Dn];
__device__ __half g_wvh[Dn*Dn];
__device__ __half g_wsh[Dn*Dn];
__device__ __half g_woh[Dn*Dn];
__device__ __half g_whh[Dn*Dn];
__device__ __half g_wp1h[DFFn*Dn];
__device__ __half g_wp2h[Dn*DFFn];
__device__ __half g_qh [TOK*Dn];    // QKV q out (raw); later attn_out
__device__ __half g_t1h[TOK*Dn];    // QKV k out (raw); later ln1024 h out
__device__ __half g_gh [TOK*Dn];    // QKV v out (raw); later gate g out
__device__ __half g_ffh[TOK*DFFn];

// ---------------- helpers ----------------
__device__ __forceinline__ void mma_16816(float* c, const uint32_t* a, const uint32_t* b){
    asm volatile(
        "mma.sync.aligned.m16n8k16.row.col.f32.f16.f16.f32 "
        "{%0,%1,%2,%3}, {%4,%5,%6,%7}, {%8,%9}, {%0,%1,%2,%3};"
        : "+f"(c[0]), "+f"(c[1]), "+f"(c[2]), "+f"(c[3])
        : "r"(a[0]), "r"(a[1]), "r"(a[2]), "r"(a[3]), "r"(b[0]), "r"(b[1]));
}
__device__ __forceinline__ void ldsm_x4(uint32_t& r0, uint32_t& r1, uint32_t& r2, uint32_t& r3,
                                        uint32_t addr){
    asm volatile("ldmatrix.sync.aligned.m8n8.x4.shared.b16 {%0,%1,%2,%3}, [%4];"
        : "=r"(r0), "=r"(r1), "=r"(r2), "=r"(r3) : "r"(addr));
}
__device__ __forceinline__ void cpa16(void* dst, const void* src){
    uint32_t d = (uint32_t)__cvta_generic_to_shared(dst);
    asm volatile("cp.async.ca.shared.global [%0], [%1], 16;" :: "r"(d), "l"(src));
}
#define CP_COMMIT() asm volatile("cp.async.commit_group;" ::: "memory")
#define CP_WAIT(N)  asm volatile("cp.async.wait_group %0;" :: "n"(N) : "memory")

// ---------------- batched fp32 -> fp16 conversion + colsum init ----------------
struct CV10 { const float* s[9]; __half* d[9]; int n[9]; float* cs; int ncs; };
__global__ void conv_f2h(CV10 cb)
{
    const int m = blockIdx.y;
    int i = (blockIdx.x * 256 + threadIdx.x) * 4;
    if (m == 9){
        if (i < cb.ncs){
            float4 u = { 1.f/1024.f, 1.f/1024.f, 1.f/1024.f, 1.f/1024.f };
            *(float4*)(cb.cs + i) = u;
        }
        return;
    }
    const float* s = cb.s[m];
    __half* d = cb.d[m];
    if (i < cb.n[m]){
        float4 v = *(const float4*)(s + i);
        __half2 h0 = __floats2half2_rn(v.x, v.y);
        __half2 h1 = __floats2half2_rn(v.z, v.w);
        uint2 u = { *(uint32_t*)&h0, *(uint32_t*)&h1 };
        *(uint2*)(d + i) = u;
    }
}

// batch descriptor (kernel param by value; blockIdx.z selects)
struct GB {
    const __half* W[4];
    float*        C[4];
    __half*       Ch[4];
    const float*  bias[4];
};

// ---------------- fp16 mma.sync GEMM (m16n8k16, BK=32, cp.async 3-stage, LDSM) ----
// C[M,N] = A[M,K] @ W[N,K]^T (+bias)(+relu); A, W fp16; accum fp32.
// Block 256 thr (8 warps, 2x4), warp tile 64x32, BK=32, fragment loads via
// ldmatrix.x4 (conflict-free on the 80B row stride). flags bit0 = relu.
__global__ void __launch_bounds__(256, 2)
gemm_h(const __half* __restrict__ A, GB gb,
       int K, int lda, int ldb, int ldc, int flags)
{
    extern __shared__ __half sm[];
    __half (*As)[128][40] = (__half(*)[128][40])sm;
    __half (*Bs)[128][40] = (__half(*)[128][40])(sm + 3 * 128 * 40);

    const __half* W    = gb.W[blockIdx.z];
    float*        C    = gb.C[blockIdx.z];
    __half*       Ch   = gb.Ch[blockIdx.z];
    const float*  bias = gb.bias[blockIdx.z];

    const int tid = threadIdx.x, lane = tid & 31, wid = tid >> 5;
    const int wm = wid & 1, wn = wid >> 1;          // warp grid 2 x 4
    const int ml = lane >> 2, cl = lane & 3;

    const int r0 = tid >> 1;                // tile row 0..127
    const int kh = (tid & 1) * 16;          // k half-chunk 0 or 16 (halves)
    const __half* Ap = A + ((size_t)blockIdx.y * 128 + r0) * lda + kh;
    const __half* Wp = W + ((size_t)blockIdx.x * 128 + r0) * ldb + kh;

    // ldmatrix per-thread address offsets (bytes within a stage)
    const uint32_t smem_base = (uint32_t)__cvta_generic_to_shared(sm);
    const uint32_t bs_base   = smem_base + 3u * 128u * 40u * 2u;
    uint32_t a_off[4], b_off[2];
#pragma unroll
    for (int mt = 0; mt < 4; mt++)
        a_off[mt] = (uint32_t)(((wm * 64 + mt * 16 + (lane & 15)) * 40 +
                                ((lane >> 4) << 3)) * 2);
#pragma unroll
    for (int np = 0; np < 2; np++)
        b_off[np] = (uint32_t)(((wn * 32 + (np * 2 + (lane >> 4)) * 8 + (lane & 7)) * 40 +
                                (((lane >> 3) & 1) << 3)) * 2);

    float acc[4][4][4];
#pragma unroll
    for (int i = 0; i < 4; i++)
#pragma unroll
        for (int j = 0; j < 4; j++)
#pragma unroll
            for (int r = 0; r < 4; r++) acc[i][j][r] = 0.f;

    const int T = K >> 5;

#define ISSUE(t, s) do { \
    const __half* a_ = Ap + (size_t)(t) * 32; \
    const __half* w_ = Wp + (size_t)(t) * 32; \
    cpa16(&As[s][r0][kh],     a_);  cpa16(&As[s][r0][kh + 8], a_ + 8); \
    cpa16(&Bs[s][r0][kh],     w_);  cpa16(&Bs[s][r0][kh + 8], w_ + 8); \
    CP_COMMIT(); \
} while(0)

    ISSUE(0, 0);
    ISSUE(1, 1);

#pragma unroll 1
    for (int t = 0; t < T; t++){
        const int s = t % 3;
        if (t + 1 < T) { CP_WAIT(1); } else { CP_WAIT(0); }
        __syncthreads();

        const uint32_t stg = (uint32_t)s * (128u * 40u * 2u);
#pragma unroll
        for (int kk = 0; kk < 2; kk++){
            const uint32_t kb = (uint32_t)(kk * 32);   // 16 halves = 32 bytes
            uint32_t af[4][4], bf[4][2];
#pragma unroll
            for (int mt = 0; mt < 4; mt++)
                ldsm_x4(af[mt][0], af[mt][1], af[mt][2], af[mt][3],
                        smem_base + stg + a_off[mt] + kb);
            ldsm_x4(bf[0][0], bf[0][1], bf[1][0], bf[1][1],
                    bs_base + stg + b_off[0] + kb);
            ldsm_x4(bf[2][0], bf[2][1], bf[3][0], bf[3][1],
                    bs_base + stg + b_off[1] + kb);
#pragma unroll
            for (int mt = 0; mt < 4; mt++)
#pragma unroll
                for (int nt = 0; nt < 4; nt++)
                    mma_16816(acc[mt][nt], af[mt], bf[nt]);
        }

        if (t + 2 < T) ISSUE(t + 2, (t + 2) % 3);
    }
#undef ISSUE

    // epilogue
    const int rbase = blockIdx.y * 128 + wm * 64 + ml;
    const int cbase = blockIdx.x * 128 + wn * 32 + 2 * cl;
#pragma unroll
    for (int mt = 0; mt < 4; mt++){
#pragma unroll
        for (int nt = 0; nt < 4; nt++){
            const int row = rbase + mt * 16;
            const int col = cbase + nt * 8;
            float bx0 = 0.f, bx1 = 0.f;
            if (bias){ bx0 = bias[col]; bx1 = bias[col + 1]; }
            float v00 = acc[mt][nt][0] + bx0, v01 = acc[mt][nt][1] + bx1;
            float v10 = acc[mt][nt][2] + bx0, v11 = acc[mt][nt][3] + bx1;
            if (flags & 1){
                v00 = fmaxf(v00, 0.f); v01 = fmaxf(v01, 0.f);
                v10 = fmaxf(v10, 0.f); v11 = fmaxf(v11, 0.f);
            }
            if (C){
                float2 u0 = { v00, v01 }, u1 = { v10, v11 };
                *(float2*)&C[(size_t)row * ldc + col] = u0;
                *(float2*)&C[(size_t)(row + 8) * ldc + col] = u1;
            }
            if (Ch){
                __half2 h0 = __floats2half2_rn(v00, v01);
                __half2 h1 = __floats2half2_rn(v10, v11);
                *(__half2*)&Ch[(size_t)row * ldc + col] = h0;
                *(__half2*)&Ch[(size_t)(row + 8) * ldc + col] = h1;
            }
        }
    }
}
#define GEMM_SMEM (3 * 128 * 40 * 2 * 2)   // 61440 B dynamic

// ---------------- block reduction helper ----------------
__device__ __forceinline__ float2 blockReduce2(float a, float b)
{
    __shared__ float sa[8], sb[8];
    int lane = threadIdx.x & 31, w = threadIdx.x >> 5;
#pragma unroll
    for (int off = 16; off; off >>= 1) {
        a += __shfl_xor_sync(0xffffffffu, a, off);
        b += __shfl_xor_sync(0xffffffffu, b, off);
    }
    __syncthreads();
    if (lane == 0) { sa[w] = a; sb[w] = b; }
    __syncthreads();
    float ra = 0.f, rb = 0.f;
#pragma unroll
    for (int i = 0; i < 8; i++) { ra += sa[i]; rb += sb[i]; }
    return make_float2(ra, rb);
}

// ---------------- layernorm over D=1024 (+opt residual, +opt fp32/fp16 out) -------
__global__ void ln1024_kernel(const float* __restrict__ in, const float* __restrict__ res,
                              const float* __restrict__ g, const float* __restrict__ b,
                              float* __restrict__ out, __half* __restrict__ outh)
{
    int row = blockIdx.x, tid = threadIdx.x;
    size_t base = (size_t)row * 1024 + tid * 4;
    float4 v = *(const float4*)(in + base);
    float x[4] = { v.x, v.y, v.z, v.w };
    if (res) {
        float4 rv = *(const float4*)(res + base);
        x[0] += rv.x; x[1] += rv.y; x[2] += rv.z; x[3] += rv.w;
    }
    float sa = 0.f, sb = 0.f;
#pragma unroll
    for (int i = 0; i < 4; i++) { sa += x[i]; sb += x[i] * x[i]; }
    float2 r = blockReduce2(sa, sb);
    float mu = r.x * (1.f / 1024.f);
    float var = r.y * (1.f / 1024.f) - mu * mu;
    float rs = rsqrtf(var + EPSF);
    float4 g4 = *(const float4*)(g + tid * 4);
    float4 b4 = *(const float4*)(b + tid * 4);
    float4 o;
    o.x = (x[0] - mu) * rs * g4.x + b4.x;
    o.y = (x[1] - mu) * rs * g4.y + b4.y;
    o.z = (x[2] - mu) * rs * g4.z + b4.z;
    o.w = (x[3] - mu) * rs * g4.w + b4.w;
    if (out) *(float4*)(out + base) = o;
    if (outh){
        __half2 h0 = __floats2half2_rn(o.x, o.y);
        __half2 h1 = __floats2half2_rn(o.z, o.w);
        uint2 u = { *(uint32_t*)&h0, *(uint32_t*)&h1 };
        *(uint2*)(outh + base) = u;
    }
}

// ---------------- fused gate (fp32 g out + fp16 g out) ----------------------------
__global__ void gate_kernel(const float* __restrict__ sp, const float* __restrict__ hp,
                            const float* __restrict__ bf,
                            const float* __restrict__ gg, const float* __restrict__ gb,
                            float* __restrict__ out, __half* __restrict__ outh)
{
    int row = blockIdx.x, tid = threadIdx.x;
    size_t base = (size_t)row * 1024 + tid * 4;
    float4 sv = *(const float4*)(sp + base);
    float4 hv = *(const float4*)(hp + base);
    float s[4] = { sv.x, sv.y, sv.z, sv.w };
    float h[4] = { hv.x, hv.y, hv.z, hv.w };

    float sa = 0.f, sb = 0.f;
#pragma unroll
    for (int i = 0; i < 4; i++) { sa += s[i]; sb += s[i] * s[i]; }
    float2 r = blockReduce2(sa, sb);
    float mus = r.x * (1.f / 1024.f);
    float rs = rsqrtf(r.y * (1.f / 1024.f) - mus * mus + EPSF);

    sa = 0.f; sb = 0.f;
#pragma unroll
    for (int i = 0; i < 4; i++) { sa += h[i]; sb += h[i] * h[i]; }
    r = blockReduce2(sa, sb);
    float muh = r.x * (1.f / 1024.f);
    float rh = rsqrtf(r.y * (1.f / 1024.f) - muh * muh + EPSF);

    float4 g4 = *(const float4*)(gg + tid * 4);
    float4 b4 = *(const float4*)(gb + tid * 4);
    float4 f4 = *(const float4*)(bf + tid * 4);
    float gA[4] = { g4.x, g4.y, g4.z, g4.w };
    float bA[4] = { b4.x, b4.y, b4.z, b4.w };
    float fA[4] = { f4.x, f4.y, f4.z, f4.w };

    float t[4];
    sa = 0.f; sb = 0.f;
#pragma unroll
    for (int i = 0; i < 4; i++) {
        float sf = (s[i] - mus) * rs * gA[i] + bA[i];
        float hf = (h[i] - muh) * rh * gA[i] + bA[i];
        float f = 1.f / (1.f + expf(-(sf + hf + fA[i])));
        float ti = f * sf + (1.f - f) * hf;
        t[i] = ti; sa += ti; sb += ti * ti;
    }
    r = blockReduce2(sa, sb);
    float mut = r.x * (1.f / 1024.f);
    float rt = rsqrtf(r.y * (1.f / 1024.f) - mut * mut + EPSF);
    float4 o;
    o.x = (t[0] - mut) * rt * gA[0] + bA[0];
    o.y = (t[1] - mut) * rt * gA[1] + bA[1];
    o.z = (t[2] - mut) * rt * gA[2] + bA[2];
    o.w = (t[3] - mut) * rt * gA[3] + bA[3];
    *(float4*)(out + base) = o;
    __half2 h0 = __floats2half2_rn(o.x, o.y);
    __half2 h1 = __floats2half2_rn(o.z, o.w);
    uint2 u = { *(uint32_t*)&h0, *(uint32_t*)&h1 };
    *(uint2*)(outh + base) = u;
}

// ---------------- banded attention colsum via fp16 MMA + fused per-head LN --------
__global__ void __launch_bounds__(256)
attn_mma(const __half* __restrict__ qh, const __half* __restrict__ kh,
         const float* __restrict__ lng, const float* __restrict__ lnb,
         float* __restrict__ colsum)
{
    __shared__ __half Qs[32][72];
    __shared__ __half Ks[128][72];
    __shared__ float csm[128];
    __shared__ float pmax[32][4];
    __shared__ float psum[32][4];

    const int tid = threadIdx.x, lane = tid & 31, wid = tid >> 5;
    const int wm = wid & 1, wn = wid >> 1;      // warp grid 2(m) x 4(n)
    const int ml = lane >> 2, cl = lane & 3;
    const int nb = blockIdx.z, hh = blockIdx.y;
    const int qb0 = blockIdx.x * 32;
    const int kb0 = qb0 - 96;

    if (tid < 128) csm[tid] = 0.f;

    {
        int row = tid >> 3, seg = tid & 7;
        const __half* src = qh + (((size_t)nb * Sn + qb0 + row) * Hn + hh) * 64 + seg * 8;
        cpa16(&Qs[row][seg * 8], src);
    }
#pragma unroll
    for (int i = 0; i < 4; i++){
        int idx = tid + i * 256;
        int row = idx >> 3, seg = idx & 7;
        int kg = kb0 + row;
        if (kg >= 0){
            const __half* src = kh + (((size_t)nb * Sn + kg) * Hn + hh) * 64 + seg * 8;
            cpa16(&Ks[row][seg * 8], src);
        } else {
            uint4 z = {0u, 0u, 0u, 0u};
            *(uint4*)&Ks[row][seg * 8] = z;
        }
    }
    CP_COMMIT();
    CP_WAIT(0);
    __syncthreads();

    // fused per-head LN of all 160 rows (warp-per-row, 20 rows/warp)
    {
        const float gv0 = lng[lane], gv1 = lng[lane + 32];
        const float bv0 = lnb[lane], bv1 = lnb[lane + 32];
        for (int r = wid; r < 160; r += 8){
            __half* rowp = (r < 32) ? &Qs[r][0] : &Ks[r - 32][0];
            float v0 = __half2float(rowp[lane]);
            float v1 = __half2float(rowp[lane + 32]);
            float s = v0 + v1;
#pragma unroll
            for (int o = 16; o; o >>= 1) s += __shfl_xor_sync(0xffffffffu, s, o);
            float mu = s * (1.f / 64.f);
            float d0 = v0 - mu, d1 = v1 - mu;
            float qq = d0 * d0 + d1 * d1;
#pragma unroll
            for (int o = 16; o; o >>= 1) qq += __shfl_xor_sync(0xffffffffu, qq, o);
            float rr = rsqrtf(qq * (1.f / 64.f) + EPSF);
            rowp[lane]      = __float2half(d0 * rr * gv0 + bv0);
            rowp[lane + 32] = __float2half(d1 * rr * gv1 + bv1);
        }
    }
    __syncthreads();

    const uint32_t* Qu = (const uint32_t*)Qs;    // 36 u32 per row
    const uint32_t* Ku = (const uint32_t*)Ks;

    float c[4][4];
#pragma unroll
    for (int nt = 0; nt < 4; nt++)
#pragma unroll
        for (int j = 0; j < 4; j++) c[nt][j] = 0.f;

    const int m = wm * 16 + ml;
#pragma unroll
    for (int kk = 0; kk < 4; kk++){
        uint32_t af[4], bf[4][2];
        af[0] = Qu[m * 36 + kk * 8 + cl];
        af[1] = Qu[(m + 8) * 36 + kk * 8 + cl];
        af[2] = Qu[m * 36 + kk * 8 + cl + 4];
        af[3] = Qu[(m + 8) * 36 + kk * 8 + cl + 4];
#pragma unroll
        for (int nt = 0; nt < 4; nt++){
            const int n = wn * 32 + nt * 8 + ml;
            bf[nt][0] = Ku[n * 36 + kk * 8 + cl];
            bf[nt][1] = Ku[n * 36 + kk * 8 + cl + 4];
        }
#pragma unroll
        for (int nt = 0; nt < 4; nt++)
            mma_16816(c[nt], af, bf[nt]);
    }

    const int r_lo = wm * 16 + ml, r_hi = r_lo + 8;
    float lg[4][4];
    float mx_lo = -3.4e38f, mx_hi = -3.4e38f;
#pragma unroll
    for (int nt = 0; nt < 4; nt++){
#pragma unroll
        for (int j = 0; j < 4; j++){
            int col = wn * 32 + nt * 8 + 2 * cl + (j & 1);
            int row = (j < 2) ? r_lo : r_hi;
            int qg = qb0 + row, kg = kb0 + col;
            bool valid = (qg >= 1) && (kg >= 0) && (col >= row) && (col < row + 96);
            float v = valid ? c[nt][j] * 0.03125f - (float)(96 + row - col) : -3.4e38f;
            lg[nt][j] = v;
            if (j < 2) mx_lo = fmaxf(mx_lo, v); else mx_hi = fmaxf(mx_hi, v);
        }
    }
    mx_lo = fmaxf(mx_lo, __shfl_xor_sync(0xffffffffu, mx_lo, 1));
    mx_lo = fmaxf(mx_lo, __shfl_xor_sync(0xffffffffu, mx_lo, 2));
    mx_hi = fmaxf(mx_hi, __shfl_xor_sync(0xffffffffu, mx_hi, 1));
    mx_hi = fmaxf(mx_hi, __shfl_xor_sync(0xffffffffu, mx_hi, 2));
    if (cl == 0){ pmax[r_lo][wn] = mx_lo; pmax[r_hi][wn] = mx_hi; }
    __syncthreads();
    float rm_lo = fmaxf(fmaxf(pmax[r_lo][0], pmax[r_lo][1]),
                        fmaxf(pmax[r_lo][2], pmax[r_lo][3]));
    float rm_hi = fmaxf(fmaxf(pmax[r_hi][0], pmax[r_hi][1]),
                        fmaxf(pmax[r_hi][2], pmax[r_hi][3]));

    float p[4][4];
    float s_lo = 0.f, s_hi = 0.f;
#pragma unroll
    for (int nt = 0; nt < 4; nt++){
#pragma unroll
        for (int j = 0; j < 4; j++){
            float v = lg[nt][j];
            float e = (v > -1e30f) ? expf(v - ((j < 2) ? rm_lo : rm_hi)) : 0.f;
            p[nt][j] = e;
            if (j < 2) s_lo += e; else s_hi += e;
        }
    }
    s_lo += __shfl_xor_sync(0xffffffffu, s_lo, 1);
    s_lo += __shfl_xor_sync(0xffffffffu, s_lo, 2);
    s_hi += __shfl_xor_sync(0xffffffffu, s_hi, 1);
    s_hi += __shfl_xor_sync(0xffffffffu, s_hi, 2);
    if (cl == 0){ psum[r_lo][wn] = s_lo; psum[r_hi][wn] = s_hi; }
    __syncthreads();
    float Z_lo = psum[r_lo][0] + psum[r_lo][1] + psum[r_lo][2] + psum[r_lo][3];
    float Z_hi = psum[r_hi][0] + psum[r_hi][1] + psum[r_hi][2] + psum[r_hi][3];
    float iz_lo = (Z_lo > 0.f) ? 1.f / Z_lo : 0.f;
    float iz_hi = (Z_hi > 0.f) ? 1.f / Z_hi : 0.f;

#pragma unroll
    for (int nt = 0; nt < 4; nt++){
#pragma unroll
        for (int j = 0; j < 4; j++){
            float val = p[nt][j] * ((j < 2) ? iz_lo : iz_hi);
            if (val != 0.f){
                int col = wn * 32 + nt * 8 + 2 * cl + (j & 1);
                atomicAdd(&csm[col], val);
            }
        }
    }
    __syncthreads();

    float* dst = colsum + (size_t)(nb * Hn + hh) * Sn;
    for (int i = tid; i < 128; i += 256){
        int kg = kb0 + i;
        if (kg >= 0 && csm[i] != 0.f) atomicAdd(&dst[kg], csm[i]);
    }
}

// ---------------- fused LN(v) * colsum -> attn_out (fp16), warp-per-head-row ------
__global__ void ln_scale_v(const __half* __restrict__ v,
                           const float* __restrict__ g, const float* __restrict__ b,
                           const float* __restrict__ cs, __half* __restrict__ out)
{
    int row = blockIdx.x * 8 + (threadIdx.x >> 5);   // 0 .. TOK*Hn-1
    int lane = threadIdx.x & 31;
    const __half* p = v + (size_t)row * 64;
    float v0 = __half2float(p[lane]), v1 = __half2float(p[lane + 32]);
    float s = v0 + v1;
#pragma unroll
    for (int o = 16; o; o >>= 1) s += __shfl_xor_sync(0xffffffffu, s, o);
    float mu = s * (1.f / 64.f);
    float d0 = v0 - mu, d1 = v1 - mu;
    float q = d0 * d0 + d1 * d1;
#pragma unroll
    for (int o = 16; o; o >>= 1) q += __shfl_xor_sync(0xffffffffu, q, o);
    float r = rsqrtf(q * (1.f / 64.f) + EPSF);
    int token = row >> 4, h = row & 15;
    float csv = cs[((((size_t)(token >> 10)) * Hn + h) << 10) + (token & 1023)];
    __half* o_ = out + (size_t)row * 64;
    o_[lane]      = __float2half((d0 * r * g[lane]      + b[lane])      * csv);
    o_[lane + 32] = __float2half((d1 * r * g[lane + 32] + b[lane + 32]) * csv);
}

// ---------------- host orchestration ----------------
extern "C" void kernel_launch(void* const* d_in, const int* in_sizes, int n_in,
                              void* d_out, int out_size)
{
    const float* x     = (const float*)d_in[0];
    const float* Wq    = (const float*)d_in[2];
    const float* Wk    = (const float*)d_in[3];
    const float* Wv    = (const float*)d_in[4];
    const float* ln1g  = (const float*)d_in[5];
    const float* ln1b  = (const float*)d_in[6];
    const float* Wo    = (const float*)d_in[7];
    const float* bo    = (const float*)d_in[8];
    const float* ln2g  = (const float*)d_in[9];
    const float* ln2b  = (const float*)d_in[10];
    const float* Ws    = (const float*)d_in[11];
    const float* Wh    = (const float*)d_in[12];
    const float* bf    = (const float*)d_in[13];
    const float* lnfgg = (const float*)d_in[14];
    const float* lnfgb = (const float*)d_in[15];
    const float* Wp1   = (const float*)d_in[16];
    const float* bp1   = (const float*)d_in[17];
    const float* Wp2   = (const float*)d_in[18];
    const float* bp2   = (const float*)d_in[19];
    const float* lnffg = (const float*)d_in[20];
    const float* lnffb = (const float*)d_in[21];
    float* out = (float*)d_out;

    float *gq, *t1, *t2, *t3, *cs;
    __half *xh, *wqh, *wkh, *wvh, *wsh, *woh, *whh, *wp1h, *wp2h;
    __half *qh, *t1h, *gh, *ffh;
    cudaGetSymbolAddress((void**)&gq, g_q);
    cudaGetSymbolAddress((void**)&t1, g_t1);
    cudaGetSymbolAddress((void**)&t2, g_t2);
    cudaGetSymbolAddress((void**)&t3, g_t3);
    cudaGetSymbolAddress((void**)&cs, g_cs);
    cudaGetSymbolAddress((void**)&xh,  g_xh);
    cudaGetSymbolAddress((void**)&wqh, g_wqh);
    cudaGetSymbolAddress((void**)&wkh, g_wkh);
    cudaGetSymbolAddress((void**)&wvh, g_wvh);
    cudaGetSymbolAddress((void**)&wsh, g_wsh);
    cudaGetSymbolAddress((void**)&woh, g_woh);
    cudaGetSymbolAddress((void**)&whh, g_whh);
    cudaGetSymbolAddress((void**)&wp1h, g_wp1h);
    cudaGetSymbolAddress((void**)&wp2h, g_wp2h);
    cudaGetSymbolAddress((void**)&qh,  g_qh);
    cudaGetSymbolAddress((void**)&t1h, g_t1h);
    cudaGetSymbolAddress((void**)&gh,  g_gh);
    cudaGetSymbolAddress((void**)&ffh, g_ffh);
    __half* attn_out = xh;   // xh dead after QKV/Ws GEMM; reuse for attn_out fp16

    cudaFuncSetAttribute(gemm_h, cudaFuncAttributeMaxDynamicSharedMemorySize, GEMM_SMEM);

    // convert x + all weights to fp16; slice 9 initializes colsum to 1/1024
    {
        CV10 cb;
        cb.s[0]=x;   cb.d[0]=xh;   cb.n[0]=TOK*Dn;
        cb.s[1]=Wq;  cb.d[1]=wqh;  cb.n[1]=Dn*Dn;
        cb.s[2]=Wk;  cb.d[2]=wkh;  cb.n[2]=Dn*Dn;
        cb.s[3]=Wv;  cb.d[3]=wvh;  cb.n[3]=Dn*Dn;
        cb.s[4]=Ws;  cb.d[4]=wsh;  cb.n[4]=Dn*Dn;
        cb.s[5]=Wo;  cb.d[5]=woh;  cb.n[5]=Dn*Dn;
        cb.s[6]=Wh;  cb.d[6]=whh;  cb.n[6]=Dn*Dn;
        cb.s[7]=Wp1; cb.d[7]=wp1h; cb.n[7]=DFFn*Dn;
        cb.s[8]=Wp2; cb.d[8]=wp2h; cb.n[8]=Dn*DFFn;
        cb.cs = cs; cb.ncs = Bn*Hn*Sn;
        conv_f2h<<<dim3(DFFn*Dn/4/256, 10), 256>>>(cb);
    }

    // QKV + Ws projections in one batched launch (A = xh)
    {
        GB gb;
        gb.W[0] = wqh; gb.W[1] = wkh; gb.W[2] = wvh; gb.W[3] = wsh;
        gb.C[0] = nullptr; gb.C[1] = nullptr; gb.C[2] = nullptr; gb.C[3] = t2;
        gb.Ch[0] = qh; gb.Ch[1] = t1h; gb.Ch[2] = gh; gb.Ch[3] = nullptr;
        gb.bias[0] = gb.bias[1] = gb.bias[2] = gb.bias[3] = nullptr;
        gemm_h<<<dim3(8, 32, 4), 256, GEMM_SMEM>>>(xh, gb, Dn, Dn, Dn, Dn, 0);
    }

    // banded attention colsum (raw q,k; LN fused in-kernel)
    attn_mma<<<dim3(Sn / 32, Hn, Bn), 256>>>(qh, t1h, ln1g, ln1b, cs);

    // attn_out (fp16) = LN(v) * colsum  (fused; writes into xh scratch)
    ln_scale_v<<<TOK * Hn / 8, 256>>>(gh, ln1g, ln1b, cs, attn_out);

    // output projection + LN -> h (t1h fp16 only)
    {
        GB gb; gb.W[0] = woh; gb.C[0] = t1; gb.Ch[0] = nullptr; gb.bias[0] = bo;
        gemm_h<<<dim3(8, 32, 1), 256, GEMM_SMEM>>>(attn_out, gb, Dn, Dn, Dn, Dn, 0);
    }
    ln1024_kernel<<<TOK, 256>>>(t1, nullptr, ln2g, ln2b, nullptr, t1h);

    // fusion gate (t2 = x@Ws^T computed above)
    {
        GB gb; gb.W[0] = whh; gb.C[0] = t3; gb.Ch[0] = nullptr; gb.bias[0] = nullptr;
        gemm_h<<<dim3(8, 32, 1), 256, GEMM_SMEM>>>(t1h, gb, Dn, Dn, Dn, Dn, 0);
    }
    gate_kernel<<<TOK, 256>>>(t2, t3, bf, lnfgg, lnfgb, gq, gh);  // g fp32 -> gq, fp16 -> gh

    // FFN (FFN1 writes fp16 only; FFN2 fp32)
    {
        GB gb; gb.W[0] = wp1h; gb.C[0] = nullptr; gb.Ch[0] = ffh; gb.bias[0] = bp1;
        gemm_h<<<dim3(32, 32, 1), 256, GEMM_SMEM>>>(gh, gb, Dn, Dn, Dn, DFFn, 1);
    }
    {
        GB gb; gb.W[0] = wp2h; gb.C[0] = t3; gb.Ch[0] = nullptr; gb.bias[0] = bp2;
        gemm_h<<<dim3(8, 32, 1), 256, GEMM_SMEM>>>(ffh, gb, DFFn, DFFn, DFFn, Dn, 0);
    }

    // final residual + LN
    ln1024_kernel<<<TOK, 256>>>(t3, gq, lnffg, lnffb, out, nullptr);
}